// round 3
// baseline (speedup 1.0000x reference)
#include <cuda_runtime.h>

#define E_NUM 1024
#define D_DIM 256
#define N_TOT 32768
#define ZQ_ELEMS 8388608   // N_TOT * D_DIM = 64*512*256
#define DECAY_F 0.99f
#define OMD_F 0.01f
#define EPS_F 1e-5f

// -------- device scratch (no allocations allowed) --------
__device__ float g_counts[E_NUM];
__device__ float g_embed[E_NUM * D_DIM];
__device__ float g_csq[E_NUM];
__device__ float g_loss;
__device__ float g_n;
__device__ int   g_idx[N_TOT];

// -------- zero accumulators (must run every launch: graph replays) --------
__global__ void zero_kernel() {
    int i = blockIdx.x * blockDim.x + threadIdx.x;
    if (i < E_NUM * D_DIM) g_embed[i] = 0.f;
    if (i < E_NUM) g_counts[i] = 0.f;
    if (i == 0) g_loss = 0.f;
}

// -------- codebook squared norms --------
__global__ void csq_kernel(const float* __restrict__ cb) {
    int e = blockIdx.x;
    int t = threadIdx.x;  // 64 threads
    float4 v = *(const float4*)&cb[(size_t)e * D_DIM + t * 4];
    float s = v.x * v.x + v.y * v.y + v.z * v.z + v.w * v.w;
    #pragma unroll
    for (int o = 16; o; o >>= 1) s += __shfl_xor_sync(0xffffffffu, s, o);
    __shared__ float ws[2];
    if ((t & 31) == 0) ws[t >> 5] = s;
    __syncthreads();
    if (t == 0) g_csq[e] = ws[0] + ws[1];
}

// -------- fused distance-GEMM + argmin --------
// Block: 256 threads (16x16), tile 128 rows x 128 codes, 8x8 per-thread,
// K-step 8. dist = ||c||^2 - 2*x.c (row term constant for argmin).
__global__ __launch_bounds__(256, 2) void argmin_kernel(
    const float* __restrict__ z, const float* __restrict__ cb,
    float* __restrict__ idx_f_out)
{
    __shared__ __align__(16) float As[8][128];
    __shared__ __align__(16) float Bs[8][128];
    __shared__ float csm[E_NUM];
    __shared__ float rd[128][16];
    __shared__ int   ri[128][16];

    int tid  = threadIdx.x;
    int tx   = tid & 15;
    int ty   = tid >> 4;
    int row0 = blockIdx.x * 128;
    int lrow = tid >> 1;          // 0..127
    int kq   = (tid & 1) * 4;     // 0 or 4

    for (int i = tid; i < E_NUM; i += 256) csm[i] = g_csq[i];

    float bestd[8];
    int   besti[8];
    #pragma unroll
    for (int r = 0; r < 8; r++) { bestd[r] = 3.4e38f; besti[r] = 0; }

    __syncthreads();

    for (int e0 = 0; e0 < E_NUM; e0 += 128) {
        float acc[8][8];
        #pragma unroll
        for (int r = 0; r < 8; r++)
            #pragma unroll
            for (int c = 0; c < 8; c++) acc[r][c] = 0.f;

        for (int k0 = 0; k0 < D_DIM; k0 += 8) {
            float4 av = *(const float4*)&z [(size_t)(row0 + lrow) * D_DIM + k0 + kq];
            float4 bv = *(const float4*)&cb[(size_t)(e0   + lrow) * D_DIM + k0 + kq];
            __syncthreads();
            As[kq + 0][lrow] = av.x; As[kq + 1][lrow] = av.y;
            As[kq + 2][lrow] = av.z; As[kq + 3][lrow] = av.w;
            Bs[kq + 0][lrow] = bv.x; Bs[kq + 1][lrow] = bv.y;
            Bs[kq + 2][lrow] = bv.z; Bs[kq + 3][lrow] = bv.w;
            __syncthreads();
            #pragma unroll
            for (int k = 0; k < 8; k++) {
                float4 a0 = *(const float4*)&As[k][ty * 8];
                float4 a1 = *(const float4*)&As[k][ty * 8 + 4];
                float4 b0 = *(const float4*)&Bs[k][tx * 8];
                float4 b1 = *(const float4*)&Bs[k][tx * 8 + 4];
                float ar[8] = {a0.x, a0.y, a0.z, a0.w, a1.x, a1.y, a1.z, a1.w};
                float br[8] = {b0.x, b0.y, b0.z, b0.w, b1.x, b1.y, b1.z, b1.w};
                #pragma unroll
                for (int r = 0; r < 8; r++)
                    #pragma unroll
                    for (int c = 0; c < 8; c++) acc[r][c] += ar[r] * br[c];
            }
        }

        // distances + running argmin (ascending code order; strict < = first min)
        #pragma unroll
        for (int c = 0; c < 8; c++) {
            int code = e0 + tx * 8 + c;
            float cs = csm[code];
            #pragma unroll
            for (int r = 0; r < 8; r++) {
                float dist = cs - 2.f * acc[r][c];
                if (dist < bestd[r]) { bestd[r] = dist; besti[r] = code; }
            }
        }
    }

    #pragma unroll
    for (int r = 0; r < 8; r++) {
        rd[ty * 8 + r][tx] = bestd[r];
        ri[ty * 8 + r][tx] = besti[r];
    }
    __syncthreads();
    if (tid < 128) {
        float bd = rd[tid][0];
        int   bi = ri[tid][0];
        #pragma unroll
        for (int t = 1; t < 16; t++) {      // ascending tx = ascending code blocks
            if (rd[tid][t] < bd) { bd = rd[tid][t]; bi = ri[tid][t]; }
        }
        g_idx[row0 + tid] = bi;
        idx_f_out[row0 + tid] = (float)bi;
    }
}

// -------- gather z_q, loss partials, EMA scatter stats --------
__global__ void scatter_kernel(const float* __restrict__ z,
                               const float* __restrict__ cb,
                               float* __restrict__ zq_out)
{
    int row = blockIdx.x;
    int d   = threadIdx.x;  // 256
    int e   = g_idx[row];
    size_t zi = (size_t)row * D_DIM + d;
    float x = z[zi];
    float c = cb[(size_t)e * D_DIM + d];
    zq_out[zi] = x + (c - x);          // straight-through forward, reference rounding
    float diff = x - c;
    float v = diff * diff;
    #pragma unroll
    for (int o = 16; o; o >>= 1) v += __shfl_xor_sync(0xffffffffu, v, o);
    __shared__ float ws[8];
    if ((d & 31) == 0) ws[d >> 5] = v;
    atomicAdd(&g_embed[(size_t)e * D_DIM + d], x);
    __syncthreads();
    if (d == 0) {
        float s = 0.f;
        #pragma unroll
        for (int i = 0; i < 8; i++) s += ws[i];
        atomicAdd(&g_loss, s);
        atomicAdd(&g_counts[e], 1.0f);
    }
}

// -------- cluster-size EMA, n-sum, loss write --------
__global__ void finalize1_kernel(const float* __restrict__ ema_cs,
                                 float* __restrict__ out_cs,
                                 float* __restrict__ out_loss,
                                 float inv_nd)
{
    int e = threadIdx.x;  // 1024
    float ncs = DECAY_F * ema_cs[e] + OMD_F * g_counts[e];
    out_cs[e] = ncs;
    float v = ncs;
    #pragma unroll
    for (int o = 16; o; o >>= 1) v += __shfl_xor_sync(0xffffffffu, v, o);
    __shared__ float ws[32];
    if ((e & 31) == 0) ws[e >> 5] = v;
    __syncthreads();
    if (e < 32) {
        float s = ws[e];
        #pragma unroll
        for (int o = 16; o; o >>= 1) s += __shfl_xor_sync(0xffffffffu, s, o);
        if (e == 0) {
            g_n = s;
            *out_loss = 0.5f * g_loss * inv_nd;   // COMMITMENT_COST * mean
        }
    }
}

// -------- embed-sum EMA + smoothed codebook --------
__global__ void finalize2_kernel(const float* __restrict__ ema_cs,
                                 const float* __restrict__ ema_es,
                                 float* __restrict__ out_cb,
                                 float* __restrict__ out_es)
{
    int e = blockIdx.x;
    int d = threadIdx.x;  // 256
    float n = g_n;
    float ncs = DECAY_F * ema_cs[e] + OMD_F * g_counts[e];
    float smoothed = (ncs + EPS_F) / (n + 1024.0f * EPS_F) * n;
    size_t i = (size_t)e * D_DIM + d;
    float nes = DECAY_F * ema_es[i] + OMD_F * g_embed[i];
    out_es[i] = nes;
    out_cb[i] = nes / smoothed;
}

extern "C" void kernel_launch(void* const* d_in, const int* in_sizes, int n_in,
                              void* d_out, int out_size)
{
    const float* z_e    = (const float*)d_in[0];
    const float* cb     = (const float*)d_in[1];
    const float* ema_cs = (const float*)d_in[2];
    const float* ema_es = (const float*)d_in[3];
    float* out = (float*)d_out;

    // output layout (return order, flattened):
    //   z_q              [8388608]   offset 0
    //   vq_loss          [1]         offset 8388608
    //   indices          [32768]     offset 8388609
    //   new_codebook     [262144]    offset 8421377
    //   new_cluster_size [1024]      offset 8683521
    //   new_embed_sum    [262144]    offset 8684545   (total 8946689)
    float* out_zq   = out;
    float* out_loss = out + ZQ_ELEMS;
    float* out_idx  = out + ZQ_ELEMS + 1;
    float* out_cb   = out + ZQ_ELEMS + 1 + 32768;
    float* out_cs   = out_cb + E_NUM * D_DIM;
    float* out_es   = out_cs + E_NUM;

    zero_kernel<<<(E_NUM * D_DIM + 255) / 256, 256>>>();
    csq_kernel<<<E_NUM, 64>>>(cb);
    argmin_kernel<<<N_TOT / 128, 256>>>(z_e, cb, out_idx);
    scatter_kernel<<<N_TOT, 256>>>(z_e, cb, out_zq);
    finalize1_kernel<<<1, 1024>>>(ema_cs, out_cs, out_loss,
                                  1.0f / (float)(N_TOT * D_DIM));
    finalize2_kernel<<<E_NUM, 256>>>(ema_cs, ema_es, out_cb, out_es);
}

// round 4
// speedup vs baseline: 1.0309x; 1.0309x over previous
#include <cuda_runtime.h>

#define E_NUM 1024
#define D_DIM 256
#define N_TOT 32768
#define ZQ_ELEMS 8388608   // N_TOT * D_DIM
#define DECAY_F 0.99f
#define OMD_F 0.01f
#define EPS_F 1e-5f

// -------- device scratch (no allocations allowed) --------
__device__ float g_counts[E_NUM];
__device__ float g_embed[E_NUM * D_DIM];
__device__ float g_csq[E_NUM];
__device__ float g_loss;
__device__ float g_n;
__device__ int   g_idx[N_TOT];

// -------- zero accumulators (graph replays => every launch) --------
__global__ void zero_kernel() {
    int i = blockIdx.x * blockDim.x + threadIdx.x;
    if (i < E_NUM * D_DIM) g_embed[i] = 0.f;
    if (i < E_NUM) g_counts[i] = 0.f;
    if (i == 0) g_loss = 0.f;
}

// -------- codebook squared norms --------
__global__ void csq_kernel(const float* __restrict__ cb) {
    int e = blockIdx.x;
    int t = threadIdx.x;  // 64
    float4 v = *(const float4*)&cb[(size_t)e * D_DIM + t * 4];
    float s = v.x * v.x + v.y * v.y + v.z * v.z + v.w * v.w;
    #pragma unroll
    for (int o = 16; o; o >>= 1) s += __shfl_xor_sync(0xffffffffu, s, o);
    __shared__ float ws[2];
    if ((t & 31) == 0) ws[t >> 5] = s;
    __syncthreads();
    if (t == 0) g_csq[e] = ws[0] + ws[1];
}

// -------- helpers --------
__device__ __forceinline__ void cvt_split(float x, float& h, float& l) {
    unsigned hu;
    asm("cvt.rna.tf32.f32 %0, %1;" : "=r"(hu) : "f"(x));
    h = __uint_as_float(hu);
    float r = x - h;                       // exact (Sterbenz)
    unsigned lu;
    asm("cvt.rna.tf32.f32 %0, %1;" : "=r"(lu) : "f"(r));
    l = __uint_as_float(lu);
}

__device__ __forceinline__ void mma_tf32(float* c, const unsigned* a, const unsigned* b) {
    asm volatile(
        "mma.sync.aligned.m16n8k8.row.col.f32.tf32.tf32.f32 "
        "{%0,%1,%2,%3}, {%4,%5,%6,%7}, {%8,%9}, {%0,%1,%2,%3};\n"
        : "+f"(c[0]), "+f"(c[1]), "+f"(c[2]), "+f"(c[3])
        : "r"(a[0]), "r"(a[1]), "r"(a[2]), "r"(a[3]), "r"(b[0]), "r"(b[1]));
}

// -------- fused 3xTF32 distance-GEMM + argmin + scatter epilogue --------
// 256 threads = 8 warps. Block tile 128 rows x 128 codes, warp tile 64x32.
#define KC 16
#define SPITCH 133

__global__ __launch_bounds__(256) void argmin_kernel(
    const float* __restrict__ z, const float* __restrict__ cb,
    float* __restrict__ idx_f_out, float* __restrict__ zq_out)
{
    __shared__ float As_h[KC][SPITCH], As_l[KC][SPITCH];
    __shared__ float Bs_h[KC][SPITCH], Bs_l[KC][SPITCH];
    __shared__ float csm[E_NUM];
    __shared__ float rd[128][4];
    __shared__ int   ri[128][4];
    __shared__ int   fi[128];
    __shared__ float lws[8];

    const int tid   = threadIdx.x;
    const int warp  = tid >> 5;
    const int lane  = tid & 31;
    const int tig   = lane & 3;    // thread-in-group
    const int grp   = lane >> 2;   // group id (0..7)
    const int warp_m = (warp & 1) * 64;
    const int warp_n = (warp >> 1) * 32;
    const int row0  = blockIdx.x * 128;

    const int lrow = tid >> 1;           // 0..127 (stage loader row)
    const int kb   = (tid & 1) * 8;      // 0 or 8

    for (int i = tid; i < E_NUM; i += 256) csm[i] = g_csq[i];

    float bestd[8];
    int   besti[8];
    #pragma unroll
    for (int s = 0; s < 8; s++) { bestd[s] = 3.4e38f; besti[s] = 0; }

    for (int e0 = 0; e0 < E_NUM; e0 += 128) {
        float acc[4][4][4];
        #pragma unroll
        for (int mf = 0; mf < 4; mf++)
            #pragma unroll
            for (int nf = 0; nf < 4; nf++)
                #pragma unroll
                for (int q = 0; q < 4; q++) acc[mf][nf][q] = 0.f;

        for (int k0 = 0; k0 < D_DIM; k0 += KC) {
            __syncthreads();  // previous stage fully consumed
            // ---- stage load: A (rows) and B (codes), tf32 hi/lo split ----
            {
                const float4* zp = (const float4*)&z [(size_t)(row0 + lrow) * D_DIM + k0 + kb];
                const float4* bp = (const float4*)&cb[(size_t)(e0   + lrow) * D_DIM + k0 + kb];
                float4 a0 = zp[0], a1 = zp[1];
                float4 b0 = bp[0], b1 = bp[1];
                float h, l;
                cvt_split(a0.x, h, l); As_h[kb+0][lrow] = h; As_l[kb+0][lrow] = l;
                cvt_split(a0.y, h, l); As_h[kb+1][lrow] = h; As_l[kb+1][lrow] = l;
                cvt_split(a0.z, h, l); As_h[kb+2][lrow] = h; As_l[kb+2][lrow] = l;
                cvt_split(a0.w, h, l); As_h[kb+3][lrow] = h; As_l[kb+3][lrow] = l;
                cvt_split(a1.x, h, l); As_h[kb+4][lrow] = h; As_l[kb+4][lrow] = l;
                cvt_split(a1.y, h, l); As_h[kb+5][lrow] = h; As_l[kb+5][lrow] = l;
                cvt_split(a1.z, h, l); As_h[kb+6][lrow] = h; As_l[kb+6][lrow] = l;
                cvt_split(a1.w, h, l); As_h[kb+7][lrow] = h; As_l[kb+7][lrow] = l;
                cvt_split(b0.x, h, l); Bs_h[kb+0][lrow] = h; Bs_l[kb+0][lrow] = l;
                cvt_split(b0.y, h, l); Bs_h[kb+1][lrow] = h; Bs_l[kb+1][lrow] = l;
                cvt_split(b0.z, h, l); Bs_h[kb+2][lrow] = h; Bs_l[kb+2][lrow] = l;
                cvt_split(b0.w, h, l); Bs_h[kb+3][lrow] = h; Bs_l[kb+3][lrow] = l;
                cvt_split(b1.x, h, l); Bs_h[kb+4][lrow] = h; Bs_l[kb+4][lrow] = l;
                cvt_split(b1.y, h, l); Bs_h[kb+5][lrow] = h; Bs_l[kb+5][lrow] = l;
                cvt_split(b1.z, h, l); Bs_h[kb+6][lrow] = h; Bs_l[kb+6][lrow] = l;
                cvt_split(b1.w, h, l); Bs_h[kb+7][lrow] = h; Bs_l[kb+7][lrow] = l;
            }
            __syncthreads();

            #pragma unroll
            for (int kk = 0; kk < KC; kk += 8) {
                unsigned ah[4][4], al[4][4], bh[4][2], bl[4][2];
                #pragma unroll
                for (int mf = 0; mf < 4; mf++) {
                    int r = warp_m + mf * 16 + grp;
                    ah[mf][0] = __float_as_uint(As_h[kk+tig  ][r  ]);
                    ah[mf][1] = __float_as_uint(As_h[kk+tig  ][r+8]);
                    ah[mf][2] = __float_as_uint(As_h[kk+tig+4][r  ]);
                    ah[mf][3] = __float_as_uint(As_h[kk+tig+4][r+8]);
                    al[mf][0] = __float_as_uint(As_l[kk+tig  ][r  ]);
                    al[mf][1] = __float_as_uint(As_l[kk+tig  ][r+8]);
                    al[mf][2] = __float_as_uint(As_l[kk+tig+4][r  ]);
                    al[mf][3] = __float_as_uint(As_l[kk+tig+4][r+8]);
                }
                #pragma unroll
                for (int nf = 0; nf < 4; nf++) {
                    int c = warp_n + nf * 8 + grp;
                    bh[nf][0] = __float_as_uint(Bs_h[kk+tig  ][c]);
                    bh[nf][1] = __float_as_uint(Bs_h[kk+tig+4][c]);
                    bl[nf][0] = __float_as_uint(Bs_l[kk+tig  ][c]);
                    bl[nf][1] = __float_as_uint(Bs_l[kk+tig+4][c]);
                }
                #pragma unroll
                for (int mf = 0; mf < 4; mf++)
                    #pragma unroll
                    for (int nf = 0; nf < 4; nf++) {
                        mma_tf32(acc[mf][nf], ah[mf], bh[nf]);  // hi*hi
                        mma_tf32(acc[mf][nf], al[mf], bh[nf]);  // lo*hi
                        mma_tf32(acc[mf][nf], ah[mf], bl[nf]);  // hi*lo
                    }
            }
        }

        // ---- epilogue: distances + running argmin (index tie-break) ----
        #pragma unroll
        for (int mf = 0; mf < 4; mf++)
            #pragma unroll
            for (int nf = 0; nf < 4; nf++) {
                int colb = e0 + warp_n + nf * 8 + tig * 2;
                int slo = mf * 2, shi = mf * 2 + 1;
                float d;
                d = csm[colb  ] - 2.f * acc[mf][nf][0];
                if (d < bestd[slo] || (d == bestd[slo] && colb   < besti[slo])) { bestd[slo] = d; besti[slo] = colb;   }
                d = csm[colb+1] - 2.f * acc[mf][nf][1];
                if (d < bestd[slo] || (d == bestd[slo] && colb+1 < besti[slo])) { bestd[slo] = d; besti[slo] = colb+1; }
                d = csm[colb  ] - 2.f * acc[mf][nf][2];
                if (d < bestd[shi] || (d == bestd[shi] && colb   < besti[shi])) { bestd[shi] = d; besti[shi] = colb;   }
                d = csm[colb+1] - 2.f * acc[mf][nf][3];
                if (d < bestd[shi] || (d == bestd[shi] && colb+1 < besti[shi])) { bestd[shi] = d; besti[shi] = colb+1; }
            }
    }

    // ---- reduce across the 4 lanes of each quad (same row, different cols) ----
    #pragma unroll
    for (int s = 0; s < 8; s++) {
        float bd = bestd[s]; int bi = besti[s];
        #pragma unroll
        for (int off = 1; off <= 2; off <<= 1) {
            float od = __shfl_xor_sync(0xffffffffu, bd, off);
            int   oi = __shfl_xor_sync(0xffffffffu, bi, off);
            if (od < bd || (od == bd && oi < bi)) { bd = od; bi = oi; }
        }
        if (tig == 0) {
            int row = warp_m + (s >> 1) * 16 + (s & 1) * 8 + grp;
            rd[row][warp >> 1] = bd;
            ri[row][warp >> 1] = bi;
        }
    }
    __syncthreads();

    if (tid < 128) {
        float bd = rd[tid][0]; int bi = ri[tid][0];
        #pragma unroll
        for (int g = 1; g < 4; g++) {
            float od = rd[tid][g]; int oi = ri[tid][g];
            if (od < bd || (od == bd && oi < bi)) { bd = od; bi = oi; }
        }
        g_idx[row0 + tid] = bi;
        idx_f_out[row0 + tid] = (float)bi;
        fi[tid] = bi;
        atomicAdd(&g_counts[bi], 1.0f);
    }
    __syncthreads();

    // ---- fused scatter: z_q gather, commitment loss, EMA embed sums ----
    float lsum = 0.f;
    #pragma unroll 4
    for (int j = 0; j < 32; j++) {
        int li  = tid + j * 256;            // 0..8191 float4 slots (128 rows x 64)
        int row = li >> 6;
        int q   = li & 63;
        int e   = fi[row];
        float4 xv = ((const float4*)&z [(size_t)(row0 + row) * D_DIM])[q];
        float4 cv = ((const float4*)&cb[(size_t)e * D_DIM])[q];
        float4 o;
        o.x = xv.x + (cv.x - xv.x);
        o.y = xv.y + (cv.y - xv.y);
        o.z = xv.z + (cv.z - xv.z);
        o.w = xv.w + (cv.w - xv.w);
        ((float4*)&zq_out[(size_t)(row0 + row) * D_DIM])[q] = o;
        float dx = xv.x - cv.x, dy = xv.y - cv.y, dz = xv.z - cv.z, dw = xv.w - cv.w;
        lsum += dx * dx + dy * dy + dz * dz + dw * dw;
        float* ge = &g_embed[(size_t)e * D_DIM + q * 4];
        atomicAdd(ge + 0, xv.x);
        atomicAdd(ge + 1, xv.y);
        atomicAdd(ge + 2, xv.z);
        atomicAdd(ge + 3, xv.w);
    }
    #pragma unroll
    for (int o = 16; o; o >>= 1) lsum += __shfl_xor_sync(0xffffffffu, lsum, o);
    if (lane == 0) lws[warp] = lsum;
    __syncthreads();
    if (tid == 0) {
        float s = 0.f;
        #pragma unroll
        for (int i = 0; i < 8; i++) s += lws[i];
        atomicAdd(&g_loss, s);
    }
}

// -------- cluster-size EMA, n-sum, loss write --------
__global__ void finalize1_kernel(const float* __restrict__ ema_cs,
                                 float* __restrict__ out_cs,
                                 float* __restrict__ out_loss,
                                 float inv_nd)
{
    int e = threadIdx.x;  // 1024
    float ncs = DECAY_F * ema_cs[e] + OMD_F * g_counts[e];
    out_cs[e] = ncs;
    float v = ncs;
    #pragma unroll
    for (int o = 16; o; o >>= 1) v += __shfl_xor_sync(0xffffffffu, v, o);
    __shared__ float ws[32];
    if ((e & 31) == 0) ws[e >> 5] = v;
    __syncthreads();
    if (e < 32) {
        float s = ws[e];
        #pragma unroll
        for (int o = 16; o; o >>= 1) s += __shfl_xor_sync(0xffffffffu, s, o);
        if (e == 0) {
            g_n = s;
            *out_loss = 0.5f * g_loss * inv_nd;
        }
    }
}

// -------- embed-sum EMA + smoothed codebook --------
__global__ void finalize2_kernel(const float* __restrict__ ema_cs,
                                 const float* __restrict__ ema_es,
                                 float* __restrict__ out_cb,
                                 float* __restrict__ out_es)
{
    int e = blockIdx.x;
    int d = threadIdx.x;  // 256
    float n = g_n;
    float ncs = DECAY_F * ema_cs[e] + OMD_F * g_counts[e];
    float smoothed = (ncs + EPS_F) / (n + 1024.0f * EPS_F) * n;
    size_t i = (size_t)e * D_DIM + d;
    float nes = DECAY_F * ema_es[i] + OMD_F * g_embed[i];
    out_es[i] = nes;
    out_cb[i] = nes / smoothed;
}

extern "C" void kernel_launch(void* const* d_in, const int* in_sizes, int n_in,
                              void* d_out, int out_size)
{
    const float* z_e    = (const float*)d_in[0];
    const float* cb     = (const float*)d_in[1];
    const float* ema_cs = (const float*)d_in[2];
    const float* ema_es = (const float*)d_in[3];
    float* out = (float*)d_out;

    float* out_zq   = out;
    float* out_loss = out + ZQ_ELEMS;
    float* out_idx  = out + ZQ_ELEMS + 1;
    float* out_cb   = out + ZQ_ELEMS + 1 + N_TOT;
    float* out_cs   = out_cb + E_NUM * D_DIM;
    float* out_es   = out_cs + E_NUM;

    zero_kernel<<<(E_NUM * D_DIM + 255) / 256, 256>>>();
    csq_kernel<<<E_NUM, 64>>>(cb);
    argmin_kernel<<<N_TOT / 128, 256>>>(z_e, cb, out_idx, out_zq);
    finalize1_kernel<<<1, 1024>>>(ema_cs, out_cs, out_loss,
                                  1.0f / (float)(N_TOT * D_DIM));
    finalize2_kernel<<<E_NUM, 256>>>(ema_cs, ema_es, out_cb, out_es);
}

// round 5
// speedup vs baseline: 1.1710x; 1.1359x over previous
#include <cuda_runtime.h>

#define E_NUM 1024
#define D_DIM 256
#define N_TOT 32768
#define ZQ_ELEMS 8388608   // N_TOT * D_DIM
#define DECAY_F 0.99f
#define OMD_F 0.01f
#define EPS_F 1e-5f
#define FLT_BIG 3.4e38f

// -------- device scratch (no allocations allowed) --------
__device__ float g_counts[E_NUM];
__device__ __align__(16) float g_embed[E_NUM * D_DIM];
__device__ float g_csq[E_NUM];
__device__ float g_loss;
__device__ float g_n;
__device__ int   g_cand[N_TOT * 3];

// -------- zero accumulators (graph replays => every launch) --------
__global__ void zero_kernel() {
    int i = blockIdx.x * blockDim.x + threadIdx.x;
    if (i < E_NUM * D_DIM) g_embed[i] = 0.f;
    if (i < E_NUM) g_counts[i] = 0.f;
    if (i == 0) g_loss = 0.f;
}

// -------- codebook squared norms --------
__global__ void csq_kernel(const float* __restrict__ cb) {
    int e = blockIdx.x;
    int t = threadIdx.x;  // 64
    float4 v = *(const float4*)&cb[(size_t)e * D_DIM + t * 4];
    float s = v.x * v.x + v.y * v.y + v.z * v.z + v.w * v.w;
    #pragma unroll
    for (int o = 16; o; o >>= 1) s += __shfl_xor_sync(0xffffffffu, s, o);
    __shared__ float ws[2];
    if ((t & 31) == 0) ws[t >> 5] = s;
    __syncthreads();
    if (t == 0) g_csq[e] = ws[0] + ws[1];
}

// -------- helpers --------
__device__ __forceinline__ float cvt_tf32(float x) {
    unsigned u;
    asm("cvt.rna.tf32.f32 %0, %1;" : "=r"(u) : "f"(x));
    return __uint_as_float(u);
}

__device__ __forceinline__ void mma_tf32(float* c, const unsigned* a, const unsigned* b) {
    asm volatile(
        "mma.sync.aligned.m16n8k8.row.col.f32.tf32.tf32.f32 "
        "{%0,%1,%2,%3}, {%4,%5,%6,%7}, {%8,%9}, {%0,%1,%2,%3};\n"
        : "+f"(c[0]), "+f"(c[1]), "+f"(c[2]), "+f"(c[3])
        : "r"(a[0]), "r"(a[1]), "r"(a[2]), "r"(a[3]), "r"(b[0]), "r"(b[1]));
}

// streaming top-3 insert with (d, idx) lexicographic order
__device__ __forceinline__ void ins3t(float d, int i, float* td, int* ti) {
    bool b0 = d < td[0] || (d == td[0] && i < ti[0]);
    bool b1 = d < td[1] || (d == td[1] && i < ti[1]);
    bool b2 = d < td[2] || (d == td[2] && i < ti[2]);
    if (b0)      { td[2] = td[1]; ti[2] = ti[1]; td[1] = td[0]; ti[1] = ti[0]; td[0] = d; ti[0] = i; }
    else if (b1) { td[2] = td[1]; ti[2] = ti[1]; td[1] = d; ti[1] = i; }
    else if (b2) { td[2] = d; ti[2] = i; }
}

// -------- 1xTF32 distance-GEMM + per-row top-3 candidates --------
// 256 threads = 8 warps. Block tile 128 rows x 128 codes, warp tile 64x32.
#define KC 16
#define SPITCH 133

__global__ __launch_bounds__(256) void argmin_kernel(
    const float* __restrict__ z, const float* __restrict__ cb)
{
    __shared__ float As_h[KC][SPITCH];
    __shared__ float Bs_h[KC][SPITCH];
    __shared__ float csm[E_NUM];
    __shared__ float sd[128][4][3];
    __shared__ int   si[128][4][3];

    const int tid   = threadIdx.x;
    const int warp  = tid >> 5;
    const int lane  = tid & 31;
    const int tig   = lane & 3;    // thread-in-group
    const int grp   = lane >> 2;   // group id (0..7)
    const int warp_m = (warp & 1) * 64;
    const int warp_n = (warp >> 1) * 32;
    const int row0  = blockIdx.x * 128;

    const int lrow = tid >> 1;           // 0..127 (stage loader row)
    const int kb   = (tid & 1) * 8;      // 0 or 8

    for (int i = tid; i < E_NUM; i += 256) csm[i] = g_csq[i];

    // per-thread top-3 for 8 row-slots
    float td[8][3];
    int   ti[8][3];
    #pragma unroll
    for (int s = 0; s < 8; s++)
        #pragma unroll
        for (int t = 0; t < 3; t++) { td[s][t] = FLT_BIG; ti[s][t] = 0x7fffffff; }

    for (int e0 = 0; e0 < E_NUM; e0 += 128) {
        float acc[4][4][4];
        #pragma unroll
        for (int mf = 0; mf < 4; mf++)
            #pragma unroll
            for (int nf = 0; nf < 4; nf++)
                #pragma unroll
                for (int q = 0; q < 4; q++) acc[mf][nf][q] = 0.f;

        for (int k0 = 0; k0 < D_DIM; k0 += KC) {
            __syncthreads();  // previous stage fully consumed
            {
                const float4* zp = (const float4*)&z [(size_t)(row0 + lrow) * D_DIM + k0 + kb];
                const float4* bp = (const float4*)&cb[(size_t)(e0   + lrow) * D_DIM + k0 + kb];
                float4 a0 = zp[0], a1 = zp[1];
                float4 b0 = bp[0], b1 = bp[1];
                As_h[kb+0][lrow] = cvt_tf32(a0.x);
                As_h[kb+1][lrow] = cvt_tf32(a0.y);
                As_h[kb+2][lrow] = cvt_tf32(a0.z);
                As_h[kb+3][lrow] = cvt_tf32(a0.w);
                As_h[kb+4][lrow] = cvt_tf32(a1.x);
                As_h[kb+5][lrow] = cvt_tf32(a1.y);
                As_h[kb+6][lrow] = cvt_tf32(a1.z);
                As_h[kb+7][lrow] = cvt_tf32(a1.w);
                Bs_h[kb+0][lrow] = cvt_tf32(b0.x);
                Bs_h[kb+1][lrow] = cvt_tf32(b0.y);
                Bs_h[kb+2][lrow] = cvt_tf32(b0.z);
                Bs_h[kb+3][lrow] = cvt_tf32(b0.w);
                Bs_h[kb+4][lrow] = cvt_tf32(b1.x);
                Bs_h[kb+5][lrow] = cvt_tf32(b1.y);
                Bs_h[kb+6][lrow] = cvt_tf32(b1.z);
                Bs_h[kb+7][lrow] = cvt_tf32(b1.w);
            }
            __syncthreads();

            #pragma unroll
            for (int kk = 0; kk < KC; kk += 8) {
                unsigned ah[4][4], bh[4][2];
                #pragma unroll
                for (int mf = 0; mf < 4; mf++) {
                    int r = warp_m + mf * 16 + grp;
                    ah[mf][0] = __float_as_uint(As_h[kk+tig  ][r  ]);
                    ah[mf][1] = __float_as_uint(As_h[kk+tig  ][r+8]);
                    ah[mf][2] = __float_as_uint(As_h[kk+tig+4][r  ]);
                    ah[mf][3] = __float_as_uint(As_h[kk+tig+4][r+8]);
                }
                #pragma unroll
                for (int nf = 0; nf < 4; nf++) {
                    int c = warp_n + nf * 8 + grp;
                    bh[nf][0] = __float_as_uint(Bs_h[kk+tig  ][c]);
                    bh[nf][1] = __float_as_uint(Bs_h[kk+tig+4][c]);
                }
                #pragma unroll
                for (int mf = 0; mf < 4; mf++)
                    #pragma unroll
                    for (int nf = 0; nf < 4; nf++)
                        mma_tf32(acc[mf][nf], ah[mf], bh[nf]);
            }
        }

        // epilogue: approx distances -> streaming top-3 per row-slot
        #pragma unroll
        for (int mf = 0; mf < 4; mf++)
            #pragma unroll
            for (int nf = 0; nf < 4; nf++) {
                int colb = e0 + warp_n + nf * 8 + tig * 2;
                int slo = mf * 2, shi = mf * 2 + 1;
                ins3t(csm[colb  ] - 2.f * acc[mf][nf][0], colb,   td[slo], ti[slo]);
                ins3t(csm[colb+1] - 2.f * acc[mf][nf][1], colb+1, td[slo], ti[slo]);
                ins3t(csm[colb  ] - 2.f * acc[mf][nf][2], colb,   td[shi], ti[shi]);
                ins3t(csm[colb+1] - 2.f * acc[mf][nf][3], colb+1, td[shi], ti[shi]);
            }
    }

    // merge top-3 across the 4 lanes of each quad (same rows, disjoint cols)
    #pragma unroll
    for (int s = 0; s < 8; s++) {
        #pragma unroll
        for (int off = 1; off <= 2; off <<= 1) {
            float od[3]; int oi[3];
            #pragma unroll
            for (int t = 0; t < 3; t++) {
                od[t] = __shfl_xor_sync(0xffffffffu, td[s][t], off);
                oi[t] = __shfl_xor_sync(0xffffffffu, ti[s][t], off);
            }
            #pragma unroll
            for (int t = 0; t < 3; t++) ins3t(od[t], oi[t], td[s], ti[s]);
        }
        if (tig == 0) {
            int row = warp_m + (s >> 1) * 16 + (s & 1) * 8 + grp;
            #pragma unroll
            for (int t = 0; t < 3; t++) {
                sd[row][warp >> 1][t] = td[s][t];
                si[row][warp >> 1][t] = ti[s][t];
            }
        }
    }
    __syncthreads();

    if (tid < 128) {
        float bd[3] = {FLT_BIG, FLT_BIG, FLT_BIG};
        int   bi[3] = {0x7fffffff, 0x7fffffff, 0x7fffffff};
        #pragma unroll
        for (int g = 0; g < 4; g++)
            #pragma unroll
            for (int t = 0; t < 3; t++)
                ins3t(sd[tid][g][t], si[tid][g][t], bd, bi);
        int row = row0 + tid;
        g_cand[row * 3 + 0] = bi[0];
        g_cand[row * 3 + 1] = bi[1];
        g_cand[row * 3 + 2] = bi[2];
    }
}

// -------- exact fp32 rescore of top-3 + fused scatter --------
// 256 threads = 8 warps, one warp per row.
__global__ __launch_bounds__(256) void rescore_kernel(
    const float* __restrict__ z, const float* __restrict__ cb,
    float* __restrict__ idx_f_out, float* __restrict__ zq_out)
{
    __shared__ float lws[8];
    const int warp = threadIdx.x >> 5;
    const int lane = threadIdx.x & 31;
    const int row  = blockIdx.x * 8 + warp;

    const float4* zp = (const float4*)&z[(size_t)row * D_DIM];
    float4 x0 = zp[lane], x1 = zp[lane + 32];

    float bd = FLT_BIG;
    int   bi = 0x7fffffff;
    #pragma unroll
    for (int c = 0; c < 3; c++) {
        int e = g_cand[row * 3 + c];
        const float4* cp = (const float4*)&cb[(size_t)e * D_DIM];
        float4 c0 = cp[lane], c1 = cp[lane + 32];
        float dot = x0.x*c0.x + x0.y*c0.y + x0.z*c0.z + x0.w*c0.w
                  + x1.x*c1.x + x1.y*c1.y + x1.z*c1.z + x1.w*c1.w;
        #pragma unroll
        for (int o = 16; o; o >>= 1) dot += __shfl_xor_sync(0xffffffffu, dot, o);
        float d = g_csq[e] - 2.f * dot;
        if (d < bd || (d == bd && e < bi)) { bd = d; bi = e; }
    }

    if (lane == 0) idx_f_out[row] = (float)bi;

    // fused scatter: z_q gather, loss partials, EMA stats
    const float4* cp = (const float4*)&cb[(size_t)bi * D_DIM];
    float4 c0 = cp[lane], c1 = cp[lane + 32];
    float4 o0, o1;
    o0.x = x0.x + (c0.x - x0.x); o0.y = x0.y + (c0.y - x0.y);
    o0.z = x0.z + (c0.z - x0.z); o0.w = x0.w + (c0.w - x0.w);
    o1.x = x1.x + (c1.x - x1.x); o1.y = x1.y + (c1.y - x1.y);
    o1.z = x1.z + (c1.z - x1.z); o1.w = x1.w + (c1.w - x1.w);
    float4* qp = (float4*)&zq_out[(size_t)row * D_DIM];
    qp[lane] = o0; qp[lane + 32] = o1;

    float dx, lsum = 0.f;
    dx = x0.x - c0.x; lsum += dx * dx;  dx = x0.y - c0.y; lsum += dx * dx;
    dx = x0.z - c0.z; lsum += dx * dx;  dx = x0.w - c0.w; lsum += dx * dx;
    dx = x1.x - c1.x; lsum += dx * dx;  dx = x1.y - c1.y; lsum += dx * dx;
    dx = x1.z - c1.z; lsum += dx * dx;  dx = x1.w - c1.w; lsum += dx * dx;
    #pragma unroll
    for (int o = 16; o; o >>= 1) lsum += __shfl_xor_sync(0xffffffffu, lsum, o);
    if (lane == 0) lws[warp] = lsum;

    // vectorized EMA embed-sum reductions
    float* ge = &g_embed[(size_t)bi * D_DIM];
    asm volatile("red.global.add.v4.f32 [%0], {%1,%2,%3,%4};"
                 :: "l"(ge + lane * 4) , "f"(x0.x), "f"(x0.y), "f"(x0.z), "f"(x0.w) : "memory");
    asm volatile("red.global.add.v4.f32 [%0], {%1,%2,%3,%4};"
                 :: "l"(ge + (lane + 32) * 4), "f"(x1.x), "f"(x1.y), "f"(x1.z), "f"(x1.w) : "memory");
    if (lane == 0) atomicAdd(&g_counts[bi], 1.0f);

    __syncthreads();
    if (threadIdx.x == 0) {
        float s = 0.f;
        #pragma unroll
        for (int i = 0; i < 8; i++) s += lws[i];
        atomicAdd(&g_loss, s);
    }
}

// -------- cluster-size EMA, n-sum, loss write --------
__global__ void finalize1_kernel(const float* __restrict__ ema_cs,
                                 float* __restrict__ out_cs,
                                 float* __restrict__ out_loss,
                                 float inv_nd)
{
    int e = threadIdx.x;  // 1024
    float ncs = DECAY_F * ema_cs[e] + OMD_F * g_counts[e];
    out_cs[e] = ncs;
    float v = ncs;
    #pragma unroll
    for (int o = 16; o; o >>= 1) v += __shfl_xor_sync(0xffffffffu, v, o);
    __shared__ float ws[32];
    if ((e & 31) == 0) ws[e >> 5] = v;
    __syncthreads();
    if (e < 32) {
        float s = ws[e];
        #pragma unroll
        for (int o = 16; o; o >>= 1) s += __shfl_xor_sync(0xffffffffu, s, o);
        if (e == 0) {
            g_n = s;
            *out_loss = 0.5f * g_loss * inv_nd;
        }
    }
}

// -------- embed-sum EMA + smoothed codebook --------
__global__ void finalize2_kernel(const float* __restrict__ ema_cs,
                                 const float* __restrict__ ema_es,
                                 float* __restrict__ out_cb,
                                 float* __restrict__ out_es)
{
    int e = blockIdx.x;
    int d = threadIdx.x;  // 256
    float n = g_n;
    float ncs = DECAY_F * ema_cs[e] + OMD_F * g_counts[e];
    float smoothed = (ncs + EPS_F) / (n + 1024.0f * EPS_F) * n;
    size_t i = (size_t)e * D_DIM + d;
    float nes = DECAY_F * ema_es[i] + OMD_F * g_embed[i];
    out_es[i] = nes;
    out_cb[i] = nes / smoothed;
}

extern "C" void kernel_launch(void* const* d_in, const int* in_sizes, int n_in,
                              void* d_out, int out_size)
{
    const float* z_e    = (const float*)d_in[0];
    const float* cb     = (const float*)d_in[1];
    const float* ema_cs = (const float*)d_in[2];
    const float* ema_es = (const float*)d_in[3];
    float* out = (float*)d_out;

    float* out_zq   = out;
    float* out_loss = out + ZQ_ELEMS;
    float* out_idx  = out + ZQ_ELEMS + 1;
    float* out_cb   = out + ZQ_ELEMS + 1 + N_TOT;
    float* out_cs   = out_cb + E_NUM * D_DIM;
    float* out_es   = out_cs + E_NUM;

    zero_kernel<<<(E_NUM * D_DIM + 255) / 256, 256>>>();
    csq_kernel<<<E_NUM, 64>>>(cb);
    argmin_kernel<<<N_TOT / 128, 256>>>(z_e, cb);
    rescore_kernel<<<N_TOT / 8, 256>>>(z_e, cb, out_idx, out_zq);
    finalize1_kernel<<<1, 1024>>>(ema_cs, out_cs, out_loss,
                                  1.0f / (float)(N_TOT * D_DIM));
    finalize2_kernel<<<E_NUM, 256>>>(ema_cs, ema_es, out_cb, out_es);
}

// round 6
// speedup vs baseline: 1.5000x; 1.2809x over previous
#include <cuda_runtime.h>

#define E_NUM 1024
#define D_DIM 256
#define N_TOT 32768
#define ZQ_ELEMS 8388608   // N_TOT * D_DIM
#define DECAY_F 0.99f
#define OMD_F 0.01f
#define EPS_F 1e-5f
#define FLT_BIG 3.4e38f

// dynamic smem layout for argmin kernel
#define SMEM_A_OFF    0        // 131072 B : A fragments, 32 slices x 2 h x 4 mf x 32 lanes x float4
#define SMEM_B_OFF    131072   // 16384 B  : B double buffer, 2 x (2 s x 16 cblk x 32 lanes x float2)
#define SMEM_CSM_OFF  147456   // 4096 B   : codebook sq norms
#define SMEM_TOTAL    151552
#define SMEM_SD_OFF   131072   // tail alias over B buffers: sd [128][4][3] floats
#define SMEM_SI_OFF   137216   // si [128][4][3] ints

// -------- device scratch (no allocations allowed) --------
__device__ float g_counts[E_NUM];
__device__ __align__(16) float g_embed[E_NUM * D_DIM];
__device__ float g_csq[E_NUM];
__device__ float g_loss;
__device__ float g_n;
__device__ int   g_cand[N_TOT * 3];

// -------- zero accumulators (graph replays => every launch) --------
__global__ void zero_kernel() {
    int i = blockIdx.x * blockDim.x + threadIdx.x;
    if (i < E_NUM * D_DIM) g_embed[i] = 0.f;
    if (i < E_NUM) g_counts[i] = 0.f;
    if (i == 0) g_loss = 0.f;
}

// -------- codebook squared norms --------
__global__ void csq_kernel(const float* __restrict__ cb) {
    int e = blockIdx.x;
    int t = threadIdx.x;  // 64
    float4 v = *(const float4*)&cb[(size_t)e * D_DIM + t * 4];
    float s = v.x * v.x + v.y * v.y + v.z * v.z + v.w * v.w;
    #pragma unroll
    for (int o = 16; o; o >>= 1) s += __shfl_xor_sync(0xffffffffu, s, o);
    __shared__ float ws[2];
    if ((t & 31) == 0) ws[t >> 5] = s;
    __syncthreads();
    if (t == 0) g_csq[e] = ws[0] + ws[1];
}

// -------- helpers --------
__device__ __forceinline__ float cvt_tf32(float x) {
    unsigned u;
    asm("cvt.rna.tf32.f32 %0, %1;" : "=r"(u) : "f"(x));
    return __uint_as_float(u);
}

__device__ __forceinline__ void mma_tf32(float* c, float4 a, float2 b) {
    asm volatile(
        "mma.sync.aligned.m16n8k8.row.col.f32.tf32.tf32.f32 "
        "{%0,%1,%2,%3}, {%4,%5,%6,%7}, {%8,%9}, {%0,%1,%2,%3};\n"
        : "+f"(c[0]), "+f"(c[1]), "+f"(c[2]), "+f"(c[3])
        : "r"(__float_as_uint(a.x)), "r"(__float_as_uint(a.y)),
          "r"(__float_as_uint(a.z)), "r"(__float_as_uint(a.w)),
          "r"(__float_as_uint(b.x)), "r"(__float_as_uint(b.y)));
}

// streaming top-3 insert with (d, idx) lexicographic order
__device__ __forceinline__ void ins3t(float d, int i, float* td, int* ti) {
    bool b0 = d < td[0] || (d == td[0] && i < ti[0]);
    bool b1 = d < td[1] || (d == td[1] && i < ti[1]);
    bool b2 = d < td[2] || (d == td[2] && i < ti[2]);
    if (b0)      { td[2] = td[1]; ti[2] = ti[1]; td[1] = td[0]; ti[1] = ti[0]; td[0] = d; ti[0] = i; }
    else if (b1) { td[2] = td[1]; ti[2] = ti[1]; td[1] = d; ti[1] = i; }
    else if (b2) { td[2] = d; ti[2] = i; }
}

// -------- pipelined 1xTF32 distance-GEMM + per-row top-3 --------
// 256 threads = 8 warps. A tile (128 rows x 256 K) resident in smem.
// B streamed in 16-wide K stages, double buffered, 1 barrier/stage.
__global__ __launch_bounds__(256, 1) void argmin_kernel(
    const float* __restrict__ z, const float* __restrict__ cb)
{
    extern __shared__ char smem[];
    float*  Af   = (float*)(smem + SMEM_A_OFF);
    float*  csm  = (float*)(smem + SMEM_CSM_OFF);

    const int tid   = threadIdx.x;
    const int warp  = tid >> 5;
    const int lane  = tid & 31;
    const int tig   = lane & 3;
    const int grp   = lane >> 2;
    const int hM    = warp & 1;          // m-half (rows 0-63 / 64-127)
    const int warp_m = hM * 64;
    const int warp_n = (warp >> 1) * 32;
    const int nblk0 = warp_n >> 3;
    const int row0  = blockIdx.x * 128;

    // ---- csm load ----
    for (int i = tid; i < E_NUM; i += 256) csm[i] = g_csq[i];

    // ---- A staging: gmem -> fragment-permuted smem (once, with rna cvt) ----
    // element (r,k): FA = (k>>3)*8 + (r>>6)*4 + ((r>>4)&3); lane_w=(r&7)*4+(k&3);
    // swizzle lane_w ^ ((k>>3)&7); comp = ((k>>2)&1)*2 + ((r>>3)&1)
    #pragma unroll 4
    for (int it = 0; it < 32; it++) {
        int li = tid + it * 256;         // 0..8191 float4 slots
        int kq = li & 63;
        int r  = li >> 6;
        float4 v = *(const float4*)&z[(size_t)(row0 + r) * D_DIM + kq * 4];
        float vv[4] = {cvt_tf32(v.x), cvt_tf32(v.y), cvt_tf32(v.z), cvt_tf32(v.w)};
        int s    = kq >> 1;
        int FA   = s * 8 + (r >> 6) * 4 + ((r >> 4) & 3);
        int sw   = s & 7;
        int comp = (kq & 1) * 2 + ((r >> 3) & 1);
        int base = FA * 32;
        #pragma unroll
        for (int t = 0; t < 4; t++) {
            int lw = (((r & 7) * 4 + t) ^ sw);
            Af[(base + lw) * 4 + comp] = vv[t];
        }
    }

    // ---- B prologue: stage 0 -> buffer 0 ----
    float4 breg[2];
    #pragma unroll
    for (int j = 0; j < 2; j++) {
        int li = tid + j * 256;
        int c = li >> 2, kq = li & 3;
        breg[j] = *(const float4*)&cb[(size_t)c * D_DIM + kq * 4];
    }
    {
        float* Bw = (float*)(smem + SMEM_B_OFF);
        #pragma unroll
        for (int j = 0; j < 2; j++) {
            int li = tid + j * 256;
            int c = li >> 2, kq = li & 3;
            int FB = (kq >> 1) * 16 + (c >> 3);
            int khalf = kq & 1;
            float vv[4] = {breg[j].x, breg[j].y, breg[j].z, breg[j].w};
            #pragma unroll
            for (int t = 0; t < 4; t++) {
                int lw = (((c & 7) * 4 + t) ^ (FB & 7));
                Bw[(FB * 32 + lw) * 2 + khalf] = vv[t];
            }
        }
    }
    __syncthreads();

    // ---- per-thread top-3 state ----
    float td[8][3];
    int   ti[8][3];
    #pragma unroll
    for (int s = 0; s < 8; s++)
        #pragma unroll
        for (int t = 0; t < 3; t++) { td[s][t] = FLT_BIG; ti[s][t] = 0x7fffffff; }

    float acc[4][4][4];
    int pb = 0;

    #pragma unroll 1
    for (int st = 0; st < 128; st++) {
        if ((st & 15) == 0) {
            #pragma unroll
            for (int mf = 0; mf < 4; mf++)
                #pragma unroll
                for (int nf = 0; nf < 4; nf++)
                    #pragma unroll
                    for (int q = 0; q < 4; q++) acc[mf][nf][q] = 0.f;
        }

        // prefetch next B stage into registers
        if (st < 127) {
            int stn = st + 1;
            int e0n = (stn >> 4) << 7;
            int k0n = (stn & 15) << 4;
            #pragma unroll
            for (int j = 0; j < 2; j++) {
                int li = tid + j * 256;
                int c = li >> 2, kq = li & 3;
                breg[j] = *(const float4*)&cb[(size_t)(e0n + c) * D_DIM + k0n + kq * 4];
            }
        }

        // compute current stage: 2 kk slices
        const float2* Bf2 = (const float2*)(smem + SMEM_B_OFF + pb * 8192);
        int sbase = (st & 15) * 2;
        #pragma unroll
        for (int kk = 0; kk < 2; kk++) {
            int s  = sbase + kk;
            int sw = s & 7;
            float4 av[4];
            #pragma unroll
            for (int mf = 0; mf < 4; mf++) {
                int FA = s * 8 + hM * 4 + mf;
                av[mf] = ((const float4*)Af)[FA * 32 + (lane ^ sw)];
            }
            float2 bv[4];
            #pragma unroll
            for (int nf = 0; nf < 4; nf++) {
                int FB = kk * 16 + nblk0 + nf;
                bv[nf] = Bf2[FB * 32 + (lane ^ (FB & 7))];
            }
            #pragma unroll
            for (int mf = 0; mf < 4; mf++)
                #pragma unroll
                for (int nf = 0; nf < 4; nf++)
                    mma_tf32(acc[mf][nf], av[mf], bv[nf]);
        }

        // end of e0 tile: distances -> streaming top-3
        if ((st & 15) == 15) {
            int e0 = (st >> 4) << 7;
            #pragma unroll
            for (int mf = 0; mf < 4; mf++)
                #pragma unroll
                for (int nf = 0; nf < 4; nf++) {
                    int colb = e0 + warp_n + nf * 8 + tig * 2;
                    int slo = mf * 2, shi = mf * 2 + 1;
                    ins3t(csm[colb  ] - 2.f * acc[mf][nf][0], colb,   td[slo], ti[slo]);
                    ins3t(csm[colb+1] - 2.f * acc[mf][nf][1], colb+1, td[slo], ti[slo]);
                    ins3t(csm[colb  ] - 2.f * acc[mf][nf][2], colb,   td[shi], ti[shi]);
                    ins3t(csm[colb+1] - 2.f * acc[mf][nf][3], colb+1, td[shi], ti[shi]);
                }
        }

        // store prefetched stage into other buffer; single barrier per stage
        if (st < 127) {
            float* Bw = (float*)(smem + SMEM_B_OFF + (1 ^ pb) * 8192);
            #pragma unroll
            for (int j = 0; j < 2; j++) {
                int li = tid + j * 256;
                int c = li >> 2, kq = li & 3;
                int FB = (kq >> 1) * 16 + (c >> 3);
                int khalf = kq & 1;
                float vv[4] = {breg[j].x, breg[j].y, breg[j].z, breg[j].w};
                #pragma unroll
                for (int t = 0; t < 4; t++) {
                    int lw = (((c & 7) * 4 + t) ^ (FB & 7));
                    Bw[(FB * 32 + lw) * 2 + khalf] = vv[t];
                }
            }
            __syncthreads();
            pb ^= 1;
        }
    }

    // ---- merge top-3 across quad lanes (same rows, disjoint cols) ----
    __syncthreads();   // before aliasing B region as sd/si
    float* sd = (float*)(smem + SMEM_SD_OFF);   // [128][4][3]
    int*   si = (int*)  (smem + SMEM_SI_OFF);

    #pragma unroll
    for (int s = 0; s < 8; s++) {
        #pragma unroll
        for (int off = 1; off <= 2; off <<= 1) {
            float od[3]; int oi[3];
            #pragma unroll
            for (int t = 0; t < 3; t++) {
                od[t] = __shfl_xor_sync(0xffffffffu, td[s][t], off);
                oi[t] = __shfl_xor_sync(0xffffffffu, ti[s][t], off);
            }
            #pragma unroll
            for (int t = 0; t < 3; t++) ins3t(od[t], oi[t], td[s], ti[s]);
        }
        if (tig == 0) {
            int row = warp_m + (s >> 1) * 16 + (s & 1) * 8 + grp;
            int g = warp >> 1;
            #pragma unroll
            for (int t = 0; t < 3; t++) {
                sd[(row * 4 + g) * 3 + t] = td[s][t];
                si[(row * 4 + g) * 3 + t] = ti[s][t];
            }
        }
    }
    __syncthreads();

    if (tid < 128) {
        float bd[3] = {FLT_BIG, FLT_BIG, FLT_BIG};
        int   bi[3] = {0x7fffffff, 0x7fffffff, 0x7fffffff};
        #pragma unroll
        for (int g = 0; g < 4; g++)
            #pragma unroll
            for (int t = 0; t < 3; t++)
                ins3t(sd[(tid * 4 + g) * 3 + t], si[(tid * 4 + g) * 3 + t], bd, bi);
        int row = row0 + tid;
        g_cand[row * 3 + 0] = bi[0];
        g_cand[row * 3 + 1] = bi[1];
        g_cand[row * 3 + 2] = bi[2];
    }
}

// -------- exact fp32 rescore of top-3 + fused scatter --------
__global__ __launch_bounds__(256) void rescore_kernel(
    const float* __restrict__ z, const float* __restrict__ cb,
    float* __restrict__ idx_f_out, float* __restrict__ zq_out)
{
    __shared__ float lws[8];
    const int warp = threadIdx.x >> 5;
    const int lane = threadIdx.x & 31;
    const int row  = blockIdx.x * 8 + warp;

    const float4* zp = (const float4*)&z[(size_t)row * D_DIM];
    float4 x0 = zp[lane], x1 = zp[lane + 32];

    float bd = FLT_BIG;
    int   bi = 0x7fffffff;
    #pragma unroll
    for (int c = 0; c < 3; c++) {
        int e = g_cand[row * 3 + c];
        const float4* cp = (const float4*)&cb[(size_t)e * D_DIM];
        float4 c0 = cp[lane], c1 = cp[lane + 32];
        float dot = x0.x*c0.x + x0.y*c0.y + x0.z*c0.z + x0.w*c0.w
                  + x1.x*c1.x + x1.y*c1.y + x1.z*c1.z + x1.w*c1.w;
        #pragma unroll
        for (int o = 16; o; o >>= 1) dot += __shfl_xor_sync(0xffffffffu, dot, o);
        float d = g_csq[e] - 2.f * dot;
        if (d < bd || (d == bd && e < bi)) { bd = d; bi = e; }
    }

    if (lane == 0) idx_f_out[row] = (float)bi;

    const float4* cp = (const float4*)&cb[(size_t)bi * D_DIM];
    float4 c0 = cp[lane], c1 = cp[lane + 32];
    float4 o0, o1;
    o0.x = x0.x + (c0.x - x0.x); o0.y = x0.y + (c0.y - x0.y);
    o0.z = x0.z + (c0.z - x0.z); o0.w = x0.w + (c0.w - x0.w);
    o1.x = x1.x + (c1.x - x1.x); o1.y = x1.y + (c1.y - x1.y);
    o1.z = x1.z + (c1.z - x1.z); o1.w = x1.w + (c1.w - x1.w);
    float4* qp = (float4*)&zq_out[(size_t)row * D_DIM];
    qp[lane] = o0; qp[lane + 32] = o1;

    float dx, lsum = 0.f;
    dx = x0.x - c0.x; lsum += dx * dx;  dx = x0.y - c0.y; lsum += dx * dx;
    dx = x0.z - c0.z; lsum += dx * dx;  dx = x0.w - c0.w; lsum += dx * dx;
    dx = x1.x - c1.x; lsum += dx * dx;  dx = x1.y - c1.y; lsum += dx * dx;
    dx = x1.z - c1.z; lsum += dx * dx;  dx = x1.w - c1.w; lsum += dx * dx;
    #pragma unroll
    for (int o = 16; o; o >>= 1) lsum += __shfl_xor_sync(0xffffffffu, lsum, o);
    if (lane == 0) lws[warp] = lsum;

    float* ge = &g_embed[(size_t)bi * D_DIM];
    asm volatile("red.global.add.v4.f32 [%0], {%1,%2,%3,%4};"
                 :: "l"(ge + lane * 4) , "f"(x0.x), "f"(x0.y), "f"(x0.z), "f"(x0.w) : "memory");
    asm volatile("red.global.add.v4.f32 [%0], {%1,%2,%3,%4};"
                 :: "l"(ge + (lane + 32) * 4), "f"(x1.x), "f"(x1.y), "f"(x1.z), "f"(x1.w) : "memory");
    if (lane == 0) atomicAdd(&g_counts[bi], 1.0f);

    __syncthreads();
    if (threadIdx.x == 0) {
        float s = 0.f;
        #pragma unroll
        for (int i = 0; i < 8; i++) s += lws[i];
        atomicAdd(&g_loss, s);
    }
}

// -------- cluster-size EMA, n-sum, loss write --------
__global__ void finalize1_kernel(const float* __restrict__ ema_cs,
                                 float* __restrict__ out_cs,
                                 float* __restrict__ out_loss,
                                 float inv_nd)
{
    int e = threadIdx.x;  // 1024
    float ncs = DECAY_F * ema_cs[e] + OMD_F * g_counts[e];
    out_cs[e] = ncs;
    float v = ncs;
    #pragma unroll
    for (int o = 16; o; o >>= 1) v += __shfl_xor_sync(0xffffffffu, v, o);
    __shared__ float ws[32];
    if ((e & 31) == 0) ws[e >> 5] = v;
    __syncthreads();
    if (e < 32) {
        float s = ws[e];
        #pragma unroll
        for (int o = 16; o; o >>= 1) s += __shfl_xor_sync(0xffffffffu, s, o);
        if (e == 0) {
            g_n = s;
            *out_loss = 0.5f * g_loss * inv_nd;
        }
    }
}

// -------- embed-sum EMA + smoothed codebook --------
__global__ void finalize2_kernel(const float* __restrict__ ema_cs,
                                 const float* __restrict__ ema_es,
                                 float* __restrict__ out_cb,
                                 float* __restrict__ out_es)
{
    int e = blockIdx.x;
    int d = threadIdx.x;  // 256
    float n = g_n;
    float ncs = DECAY_F * ema_cs[e] + OMD_F * g_counts[e];
    float smoothed = (ncs + EPS_F) / (n + 1024.0f * EPS_F) * n;
    size_t i = (size_t)e * D_DIM + d;
    float nes = DECAY_F * ema_es[i] + OMD_F * g_embed[i];
    out_es[i] = nes;
    out_cb[i] = nes / smoothed;
}

extern "C" void kernel_launch(void* const* d_in, const int* in_sizes, int n_in,
                              void* d_out, int out_size)
{
    const float* z_e    = (const float*)d_in[0];
    const float* cb     = (const float*)d_in[1];
    const float* ema_cs = (const float*)d_in[2];
    const float* ema_es = (const float*)d_in[3];
    float* out = (float*)d_out;

    float* out_zq   = out;
    float* out_loss = out + ZQ_ELEMS;
    float* out_idx  = out + ZQ_ELEMS + 1;
    float* out_cb   = out + ZQ_ELEMS + 1 + N_TOT;
    float* out_cs   = out_cb + E_NUM * D_DIM;
    float* out_es   = out_cs + E_NUM;

    cudaFuncSetAttribute(argmin_kernel,
                         cudaFuncAttributeMaxDynamicSharedMemorySize, SMEM_TOTAL);

    zero_kernel<<<(E_NUM * D_DIM + 255) / 256, 256>>>();
    csq_kernel<<<E_NUM, 64>>>(cb);
    argmin_kernel<<<N_TOT / 128, 256, SMEM_TOTAL>>>(z_e, cb);
    rescore_kernel<<<N_TOT / 8, 256>>>(z_e, cb, out_idx, out_zq);
    finalize1_kernel<<<1, 1024>>>(ema_cs, out_cs, out_loss,
                                  1.0f / (float)(N_TOT * D_DIM));
    finalize2_kernel<<<E_NUM, 256>>>(ema_cs, ema_es, out_cb, out_es);
}

// round 8
// speedup vs baseline: 2.6330x; 1.7554x over previous
#include <cuda_runtime.h>
#include <cstdint>

#define E_NUM 1024
#define D_DIM 256
#define N_TOT 32768
#define ZQ_ELEMS 8388608
#define DECAY_F 0.99f
#define OMD_F 0.01f
#define FLT_BIG 3.4e38f

// ---- dynamic smem layout (argmin kernel) ----
#define SMEM_A_OFF   0        // 65536 : A 128x256 bf16, swizzled
#define SMEM_B_OFF   65536    // 32768 : B double buffer, 2 x (128 codes x 64 k bf16)
#define SMEM_SCR_OFF 98304    // 8192  : scratch [64 rows][4 wg][4] u64
#define SMEM_RUN_OFF 106496   // 4096  : run [128][4] u64
#define SMEM_TOTAL   110592

// -------- device scratch (no allocations allowed) --------
__device__ float g_counts[E_NUM];
__device__ __align__(16) float g_embed[E_NUM * D_DIM];
__device__ float g_csq[E_NUM];
__device__ float g_loss;
__device__ float g_nb;
__device__ int   g_cand[N_TOT * 4];
__device__ __align__(16) unsigned g_cbb32[E_NUM * D_DIM / 2];   // codebook bf16

// -------- helpers --------
__device__ __forceinline__ uint32_t smem_u32(const void* p) {
    uint32_t a;
    asm("{ .reg .u64 t; cvta.to.shared.u64 t, %1; cvt.u32.u64 %0, t; }" : "=r"(a) : "l"(p));
    return a;
}
__device__ __forceinline__ unsigned bpack(float lo, float hi) {
    unsigned r;
    asm("cvt.rn.bf16x2.f32 %0, %1, %2;" : "=r"(r) : "f"(hi), "f"(lo));
    return r;
}
__device__ __forceinline__ void mma_bf16(float* c, unsigned a0, unsigned a1, unsigned a2,
                                         unsigned a3, unsigned b0, unsigned b1) {
    asm volatile("mma.sync.aligned.m16n8k16.row.col.f32.bf16.bf16.f32 "
        "{%0,%1,%2,%3}, {%4,%5,%6,%7}, {%8,%9}, {%0,%1,%2,%3};"
        : "+f"(c[0]), "+f"(c[1]), "+f"(c[2]), "+f"(c[3])
        : "r"(a0), "r"(a1), "r"(a2), "r"(a3), "r"(b0), "r"(b1));
}
#define LDSM4(r0,r1,r2,r3,addr) \
    asm volatile("ldmatrix.sync.aligned.m8n8.x4.shared.b16 {%0,%1,%2,%3}, [%4];" \
        : "=r"(r0), "=r"(r1), "=r"(r2), "=r"(r3) : "r"(addr))
__device__ __forceinline__ void cp16(unsigned dst, const void* src) {
    asm volatile("cp.async.ca.shared.global [%0], [%1], 16;"
                 :: "r"(dst), "l"(__cvta_generic_to_global(src)) : "memory");
}
#define CP_COMMIT() asm volatile("cp.async.commit_group;" ::: "memory")
#define CP_WAIT0()  asm volatile("cp.async.wait_group 0;" ::: "memory")

// orderable (dist,idx) packing: ascending u64 == lexicographic (dist, idx)
__device__ __forceinline__ unsigned long long packdi(float d, int idx) {
    unsigned u = __float_as_uint(d);
    u ^= (unsigned)(((int)u) >> 31) | 0x80000000u;
    return ((unsigned long long)u << 32) | (unsigned)idx;
}
__device__ __forceinline__ void ins4(unsigned long long v, unsigned long long* p) {
    if (v < p[3]) {
        p[3] = v;
        if (p[3] < p[2]) { unsigned long long t = p[2]; p[2] = p[3]; p[3] = t; }
        if (p[2] < p[1]) { unsigned long long t = p[1]; p[1] = p[2]; p[2] = t; }
        if (p[1] < p[0]) { unsigned long long t = p[0]; p[0] = p[1]; p[1] = t; }
    }
}

// -------- csq + bf16 codebook + zero stats + ema_cs pre-sum --------
__global__ void csq_kernel(const float* __restrict__ cb, const float* __restrict__ ema_cs) {
    int e = blockIdx.x;
    int t = threadIdx.x;  // 64
    __shared__ float ws[2];
    if (e < E_NUM) {
        float4 v = *(const float4*)&cb[(size_t)e * D_DIM + t * 4];
        ((uint2*)g_cbb32)[e * 64 + t] = make_uint2(bpack(v.x, v.y), bpack(v.z, v.w));
        float s = v.x * v.x + v.y * v.y + v.z * v.z + v.w * v.w;
        #pragma unroll
        for (int o = 16; o; o >>= 1) s += __shfl_xor_sync(0xffffffffu, s, o);
        if ((t & 31) == 0) ws[t >> 5] = s;
        ((float4*)&g_embed[(size_t)e * D_DIM])[t] = make_float4(0.f, 0.f, 0.f, 0.f);
        __syncthreads();
        if (t == 0) {
            g_csq[e] = ws[0] + ws[1];
            g_counts[e] = 0.f;
            if (e == 0) g_loss = 0.f;
        }
    } else {
        float s = 0.f;
        for (int i = t; i < E_NUM; i += 64) s += ema_cs[i];
        #pragma unroll
        for (int o = 16; o; o >>= 1) s += __shfl_xor_sync(0xffffffffu, s, o);
        if ((t & 31) == 0) ws[t >> 5] = s;
        __syncthreads();
        if (t == 0) g_nb = ws[0] + ws[1];
    }
}

// -------- bf16 HMMA distance-GEMM + per-row top-4 candidates --------
// 256 threads = 8 warps; block tile 128 rows x 128 codes; warp tile 64x32.
// A resident bf16 in smem; B cp.async double-buffered K64 stages.
__global__ __launch_bounds__(256, 2) void argmin_kernel(const float* __restrict__ z)
{
    extern __shared__ char smem[];
    const uint32_t sb  = smem_u32(smem);
    const uint32_t sbA = sb + SMEM_A_OFF;
    const uint32_t sbB = sb + SMEM_B_OFF;
    unsigned long long* scr = (unsigned long long*)(smem + SMEM_SCR_OFF);
    unsigned long long* run = (unsigned long long*)(smem + SMEM_RUN_OFF);

    const int tid  = threadIdx.x;
    const int warp = tid >> 5;
    const int lane = tid & 31;
    const int tig  = lane & 3;
    const int grp  = lane >> 2;
    const int warp_m = (warp & 1) * 64;
    const int warp_n = (warp >> 1) * 32;
    const int row0 = blockIdx.x * 128;

    // fragment address precompute (all swizzle keys collapse to lane&7)
    const int asw = lane & 7;
    const int akx = lane >> 4;
    const int bkx = (lane >> 3) & 1;
    uint32_t aB[4];
    #pragma unroll
    for (int mf = 0; mf < 4; mf++)
        aB[mf] = sbA + (warp_m + mf * 16 + ((lane >> 3) & 1) * 8 + (lane & 7)) * 512;
    const uint32_t bB0 = (uint32_t)((warp_n + ((lane >> 4)) * 8 + (lane & 7)) * 128);
    const uint32_t bB1 = (uint32_t)((warp_n + (2 + (lane >> 4)) * 8 + (lane & 7)) * 128);

    // ---- A staging: z rows -> bf16 swizzled smem ----
    #pragma unroll 4
    for (int i = 0; i < 16; i++) {
        int li = tid + i * 256;          // 4096 granules (16B = 8 bf16)
        int r = li >> 5, kg = li & 31;
        const float4* s = (const float4*)&z[(size_t)(row0 + r) * D_DIM + kg * 8];
        float4 v0 = s[0], v1 = s[1];
        *(uint4*)(smem + SMEM_A_OFF + r * 512 + ((kg ^ (r & 7)) << 4)) =
            make_uint4(bpack(v0.x, v0.y), bpack(v0.z, v0.w),
                       bpack(v1.x, v1.y), bpack(v1.z, v1.w));
    }
    // ---- B stage 0 via cp.async ----
    {
        const char* src = (const char*)g_cbb32;
        #pragma unroll
        for (int i = 0; i < 4; i++) {
            int li = tid + i * 256;      // 1024 granules
            int r = li >> 3, kg = li & 7;
            cp16(sbB + r * 128 + ((kg ^ (r & 7)) << 4), src + ((size_t)r * 256 + kg * 8) * 2);
        }
        CP_COMMIT();
    }
    if (tid < 128) {
        run[tid * 4 + 0] = ~0ULL; run[tid * 4 + 1] = ~0ULL;
        run[tid * 4 + 2] = ~0ULL; run[tid * 4 + 3] = ~0ULL;
    }
    CP_WAIT0();
    __syncthreads();

    float acc[4][4][4];
    #pragma unroll
    for (int mf = 0; mf < 4; mf++)
        #pragma unroll
        for (int nf = 0; nf < 4; nf++)
            #pragma unroll
            for (int q = 0; q < 4; q++) acc[mf][nf][q] = 0.f;

    int pb = 0;
    #pragma unroll 1
    for (int st = 0; st < 32; st++) {
        const int t = st >> 2, ks = st & 3;

        // issue next B stage (no registers held — cp.async)
        if (st < 31) {
            int stn = st + 1, tn = stn >> 2, ksn = stn & 3;
            const char* src = (const char*)g_cbb32 + ((size_t)(tn * 128) * 256 + ksn * 64) * 2;
            uint32_t dstb = sbB + (pb ^ 1) * 16384;
            #pragma unroll
            for (int i = 0; i < 4; i++) {
                int li = tid + i * 256;
                int r = li >> 3, kg = li & 7;
                cp16(dstb + r * 128 + ((kg ^ (r & 7)) << 4), src + ((size_t)r * 256 + kg * 8) * 2);
            }
            CP_COMMIT();
        }

        // compute current stage: 4 k16 slices
        const uint32_t bbuf = sbB + pb * 16384;
        #pragma unroll
        for (int k16 = 0; k16 < 4; k16++) {
            unsigned b0, b1, b2, b3, c0, c1, c2, c3;
            uint32_t kb = (uint32_t)(((k16 * 2 + bkx) ^ asw) << 4);
            LDSM4(b0, b1, b2, b3, bbuf + bB0 + kb);
            LDSM4(c0, c1, c2, c3, bbuf + bB1 + kb);
            int kga = ks * 8 + k16 * 2 + akx;
            #pragma unroll
            for (int mf = 0; mf < 4; mf++) {
                unsigned a0, a1, a2, a3;
                LDSM4(a0, a1, a2, a3, aB[mf] + ((kga ^ asw) << 4));
                mma_bf16(acc[mf][0], a0, a1, a2, a3, b0, b1);
                mma_bf16(acc[mf][1], a0, a1, a2, a3, b2, b3);
                mma_bf16(acc[mf][2], a0, a1, a2, a3, c0, c1);
                mma_bf16(acc[mf][3], a0, a1, a2, a3, c2, c3);
            }
        }

        // ---- tile epilogue: distances -> top-4 (smem-held running state) ----
        if (ks == 3) {
            int cbase = t * 128 + warp_n + tig * 2;
            float cq[8];
            #pragma unroll
            for (int nf = 0; nf < 4; nf++) {
                cq[nf * 2]     = __ldg(&g_csq[cbase + nf * 8]);
                cq[nf * 2 + 1] = __ldg(&g_csq[cbase + nf * 8 + 1]);
            }
            #pragma unroll
            for (int p = 0; p < 2; p++) {
                #pragma unroll
                for (int mi = 0; mi < 2; mi++) {
                    int mf = p * 2 + mi;
                    #pragma unroll
                    for (int rh = 0; rh < 2; rh++) {
                        unsigned long long p4[4] = {~0ULL, ~0ULL, ~0ULL, ~0ULL};
                        #pragma unroll
                        for (int nf = 0; nf < 4; nf++) {
                            ins4(packdi(cq[nf*2]   - 2.f * acc[mf][nf][rh*2],   cbase + nf*8),     p4);
                            ins4(packdi(cq[nf*2+1] - 2.f * acc[mf][nf][rh*2+1], cbase + nf*8 + 1), p4);
                        }
                        #pragma unroll
                        for (int off = 1; off <= 2; off <<= 1) {
                            unsigned long long ov[4];
                            #pragma unroll
                            for (int j = 0; j < 4; j++)
                                ov[j] = __shfl_xor_sync(0xffffffffu, p4[j], off);
                            #pragma unroll
                            for (int j = 0; j < 4; j++) ins4(ov[j], p4);
                        }
                        if (tig == 0) {
                            int lrow = (warp & 1) * 32 + mi * 16 + rh * 8 + grp;
                            unsigned long long* s = scr + (lrow * 4 + (warp >> 1)) * 4;
                            s[0] = p4[0]; s[1] = p4[1]; s[2] = p4[2]; s[3] = p4[3];
                        }
                    }
                }
                __syncthreads();
                if (tid < 64) {
                    int row = ((tid >> 5) << 6) | (p << 5) | (tid & 31);
                    unsigned long long* rr = run + row * 4;
                    unsigned long long r4[4] = {rr[0], rr[1], rr[2], rr[3]};
                    #pragma unroll
                    for (int g = 0; g < 4; g++) {
                        unsigned long long* s = scr + (tid * 4 + g) * 4;
                        ins4(s[0], r4); ins4(s[1], r4); ins4(s[2], r4); ins4(s[3], r4);
                    }
                    rr[0] = r4[0]; rr[1] = r4[1]; rr[2] = r4[2]; rr[3] = r4[3];
                }
                __syncthreads();
            }
            #pragma unroll
            for (int mf = 0; mf < 4; mf++)
                #pragma unroll
                for (int nf = 0; nf < 4; nf++)
                    #pragma unroll
                    for (int q = 0; q < 4; q++) acc[mf][nf][q] = 0.f;
        }

        CP_WAIT0();
        __syncthreads();
        pb ^= 1;
    }

    if (tid < 128) {
        int row = row0 + tid;
        #pragma unroll
        for (int k = 0; k < 4; k++)
            g_cand[row * 4 + k] = (int)(run[tid * 4 + k] & 0xFFFFFFFFULL);
    }
}

// -------- exact fp32 rescore of top-4 + fused scatter --------
__global__ __launch_bounds__(256) void rescore_kernel(
    const float* __restrict__ z, const float* __restrict__ cb,
    float* __restrict__ idx_f_out, float* __restrict__ zq_out)
{
    __shared__ float lws[8];
    const int warp = threadIdx.x >> 5;
    const int lane = threadIdx.x & 31;
    const int row  = blockIdx.x * 8 + warp;

    const float4* zp = (const float4*)&z[(size_t)row * D_DIM];
    float4 x0 = zp[lane], x1 = zp[lane + 32];

    float bd = FLT_BIG;
    int   bi = 0x7fffffff;
    #pragma unroll
    for (int c = 0; c < 4; c++) {
        int e = g_cand[row * 4 + c];
        const float4* cp = (const float4*)&cb[(size_t)e * D_DIM];
        float4 c0 = cp[lane], c1 = cp[lane + 32];
        float dot = x0.x*c0.x + x0.y*c0.y + x0.z*c0.z + x0.w*c0.w
                  + x1.x*c1.x + x1.y*c1.y + x1.z*c1.z + x1.w*c1.w;
        #pragma unroll
        for (int o = 16; o; o >>= 1) dot += __shfl_xor_sync(0xffffffffu, dot, o);
        float d = g_csq[e] - 2.f * dot;
        if (d < bd || (d == bd && e < bi)) { bd = d; bi = e; }
    }
    if (lane == 0) idx_f_out[row] = (float)bi;

    const float4* cp = (const float4*)&cb[(size_t)bi * D_DIM];
    float4 c0 = cp[lane], c1 = cp[lane + 32];
    float4 o0, o1;
    o0.x = x0.x + (c0.x - x0.x); o0.y = x0.y + (c0.y - x0.y);
    o0.z = x0.z + (c0.z - x0.z); o0.w = x0.w + (c0.w - x0.w);
    o1.x = x1.x + (c1.x - x1.x); o1.y = x1.y + (c1.y - x1.y);
    o1.z = x1.z + (c1.z - x1.z); o1.w = x1.w + (c1.w - x1.w);
    float4* qp = (float4*)&zq_out[(size_t)row * D_DIM];
    qp[lane] = o0; qp[lane + 32] = o1;

    float dx, lsum = 0.f;
    dx = x0.x - c0.x; lsum += dx * dx;  dx = x0.y - c0.y; lsum += dx * dx;
    dx = x0.z - c0.z; lsum += dx * dx;  dx = x0.w - c0.w; lsum += dx * dx;
    dx = x1.x - c1.x; lsum += dx * dx;  dx = x1.y - c1.y; lsum += dx * dx;
    dx = x1.z - c1.z; lsum += dx * dx;  dx = x1.w - c1.w; lsum += dx * dx;
    #pragma unroll
    for (int o = 16; o; o >>= 1) lsum += __shfl_xor_sync(0xffffffffu, lsum, o);
    if (lane == 0) lws[warp] = lsum;

    float* ge = &g_embed[(size_t)bi * D_DIM];
    asm volatile("red.global.add.v4.f32 [%0], {%1,%2,%3,%4};"
                 :: "l"(ge + lane * 4), "f"(x0.x), "f"(x0.y), "f"(x0.z), "f"(x0.w) : "memory");
    asm volatile("red.global.add.v4.f32 [%0], {%1,%2,%3,%4};"
                 :: "l"(ge + (lane + 32) * 4), "f"(x1.x), "f"(x1.y), "f"(x1.z), "f"(x1.w) : "memory");
    if (lane == 0) atomicAdd(&g_counts[bi], 1.0f);

    __syncthreads();
    if (threadIdx.x == 0) {
        float s = 0.f;
        #pragma unroll
        for (int i = 0; i < 8; i++) s += lws[i];
        atomicAdd(&g_loss, s);
    }
}

// -------- merged finalize --------
__global__ void finalize_kernel(const float* __restrict__ ema_cs,
                                const float* __restrict__ ema_es,
                                float* __restrict__ out_cb,
                                float* __restrict__ out_cs,
                                float* __restrict__ out_es,
                                float* __restrict__ out_loss)
{
    int e = blockIdx.x;
    int d = threadIdx.x;  // 256
    float n = DECAY_F * g_nb + OMD_F * (float)N_TOT;
    float ncs = DECAY_F * ema_cs[e] + OMD_F * g_counts[e];
    float smoothed = (ncs + 1e-5f) / (n + 1024.0f * 1e-5f) * n;
    size_t i = (size_t)e * D_DIM + d;
    float nes = DECAY_F * ema_es[i] + OMD_F * g_embed[i];
    out_es[i] = nes;
    out_cb[i] = nes / smoothed;
    if (d == 0) {
        out_cs[e] = ncs;
        if (e == 0) *out_loss = 0.5f * g_loss / (float)(N_TOT * D_DIM);
    }
}

extern "C" void kernel_launch(void* const* d_in, const int* in_sizes, int n_in,
                              void* d_out, int out_size)
{
    const float* z_e    = (const float*)d_in[0];
    const float* cb     = (const float*)d_in[1];
    const float* ema_cs = (const float*)d_in[2];
    const float* ema_es = (const float*)d_in[3];
    float* out = (float*)d_out;

    float* out_zq   = out;
    float* out_loss = out + ZQ_ELEMS;
    float* out_idx  = out + ZQ_ELEMS + 1;
    float* out_cb   = out + ZQ_ELEMS + 1 + N_TOT;
    float* out_cs   = out_cb + E_NUM * D_DIM;
    float* out_es   = out_cs + E_NUM;

    cudaFuncSetAttribute(argmin_kernel,
                         cudaFuncAttributeMaxDynamicSharedMemorySize, SMEM_TOTAL);

    csq_kernel<<<E_NUM + 1, 64>>>(cb, ema_cs);
    argmin_kernel<<<N_TOT / 128, 256, SMEM_TOTAL>>>(z_e);
    rescore_kernel<<<N_TOT / 8, 256>>>(z_e, cb, out_idx, out_zq);
    finalize_kernel<<<E_NUM, 256>>>(ema_cs, ema_es, out_cb, out_cs, out_es, out_loss);
}

// round 9
// speedup vs baseline: 4.0015x; 1.5198x over previous
#include <cuda_runtime.h>
#include <cstdint>

#define E_NUM 1024
#define D_DIM 256
#define N_TOT 32768
#define ZQ_ELEMS 8388608
#define DECAY_F 0.99f
#define OMD_F 0.01f
#define FLT_BIG 3.4e38f

// ---- dynamic smem layout (main kernel) ----
#define SMEM_A_OFF    0        // 65536 : A 128x256 bf16, swizzled
#define SMEM_B_OFF    65536    // 32768 : B double buffer, 2 x (128 codes x 64 k bf16)
#define SMEM_CAND_OFF 98304    // 6144  : cand [128 rows][2 halves][3] u64
#define SMEM_TOTAL    104448

// -------- device scratch (no allocations allowed) --------
__device__ float g_counts[E_NUM];
__device__ __align__(16) float g_embed[E_NUM * D_DIM];
__device__ float g_csq[E_NUM];
__device__ float g_loss;
__device__ float g_nb;
__device__ __align__(16) unsigned g_cbb32[E_NUM * D_DIM / 2];   // codebook bf16

// -------- helpers --------
__device__ __forceinline__ uint32_t smem_u32(const void* p) {
    uint32_t a;
    asm("{ .reg .u64 t; cvta.to.shared.u64 t, %1; cvt.u32.u64 %0, t; }" : "=r"(a) : "l"(p));
    return a;
}
__device__ __forceinline__ unsigned bpack(float lo, float hi) {
    unsigned r;
    asm("cvt.rn.bf16x2.f32 %0, %1, %2;" : "=r"(r) : "f"(hi), "f"(lo));
    return r;
}
__device__ __forceinline__ void mma_bf16(float* c, unsigned a0, unsigned a1, unsigned a2,
                                         unsigned a3, unsigned b0, unsigned b1) {
    asm volatile("mma.sync.aligned.m16n8k16.row.col.f32.bf16.bf16.f32 "
        "{%0,%1,%2,%3}, {%4,%5,%6,%7}, {%8,%9}, {%0,%1,%2,%3};"
        : "+f"(c[0]), "+f"(c[1]), "+f"(c[2]), "+f"(c[3])
        : "r"(a0), "r"(a1), "r"(a2), "r"(a3), "r"(b0), "r"(b1));
}
#define LDSM4(r0,r1,r2,r3,addr) \
    asm volatile("ldmatrix.sync.aligned.m8n8.x4.shared.b16 {%0,%1,%2,%3}, [%4];" \
        : "=r"(r0), "=r"(r1), "=r"(r2), "=r"(r3) : "r"(addr))
__device__ __forceinline__ void cp16(unsigned dst, const void* src) {
    asm volatile("cp.async.ca.shared.global [%0], [%1], 16;"
                 :: "r"(dst), "l"(__cvta_generic_to_global(src)) : "memory");
}
#define CP_COMMIT() asm volatile("cp.async.commit_group;" ::: "memory")
#define CP_WAIT0()  asm volatile("cp.async.wait_group 0;" ::: "memory")

// orderable (dist,idx) packing: ascending u64 == lexicographic (dist, idx)
__device__ __forceinline__ unsigned long long packdi(float d, int idx) {
    unsigned u = __float_as_uint(d);
    u ^= (unsigned)(((int)u) >> 31) | 0x80000000u;
    return ((unsigned long long)u << 32) | (unsigned)idx;
}
__device__ __forceinline__ void ins3(unsigned long long v, unsigned long long* p) {
    if (v < p[2]) {
        p[2] = v;
        if (p[2] < p[1]) { unsigned long long t = p[1]; p[1] = p[2]; p[2] = t; }
        if (p[1] < p[0]) { unsigned long long t = p[0]; p[0] = p[1]; p[1] = t; }
    }
}

// -------- csq + bf16 codebook + zero stats + ema_cs pre-sum --------
__global__ void csq_kernel(const float* __restrict__ cb, const float* __restrict__ ema_cs) {
    int e = blockIdx.x;
    int t = threadIdx.x;  // 64
    __shared__ float ws[2];
    if (e < E_NUM) {
        float4 v = *(const float4*)&cb[(size_t)e * D_DIM + t * 4];
        ((uint2*)g_cbb32)[e * 64 + t] = make_uint2(bpack(v.x, v.y), bpack(v.z, v.w));
        float s = v.x * v.x + v.y * v.y + v.z * v.z + v.w * v.w;
        #pragma unroll
        for (int o = 16; o; o >>= 1) s += __shfl_xor_sync(0xffffffffu, s, o);
        if ((t & 31) == 0) ws[t >> 5] = s;
        ((float4*)&g_embed[(size_t)e * D_DIM])[t] = make_float4(0.f, 0.f, 0.f, 0.f);
        __syncthreads();
        if (t == 0) {
            g_csq[e] = ws[0] + ws[1];
            g_counts[e] = 0.f;
            if (e == 0) g_loss = 0.f;
        }
    } else {
        float s = 0.f;
        for (int i = t; i < E_NUM; i += 64) s += ema_cs[i];
        #pragma unroll
        for (int o = 16; o; o >>= 1) s += __shfl_xor_sync(0xffffffffu, s, o);
        if ((t & 31) == 0) ws[t >> 5] = s;
        __syncthreads();
        if (t == 0) g_nb = ws[0] + ws[1];
    }
}

// -------- bf16 HMMA GEMM + register top-3 + fused exact rescore/scatter --------
// 256 threads = 8 warps; block tile 128 rows x 128 codes; warp tile 32x64.
__global__ __launch_bounds__(256, 2) void vq_main_kernel(
    const float* __restrict__ z, const float* __restrict__ cb,
    float* __restrict__ idx_f_out, float* __restrict__ zq_out)
{
    extern __shared__ char smem[];
    const uint32_t sb  = smem_u32(smem);
    const uint32_t sbA = sb + SMEM_A_OFF;
    const uint32_t sbB = sb + SMEM_B_OFF;
    unsigned long long* candsm = (unsigned long long*)(smem + SMEM_CAND_OFF);

    const int tid  = threadIdx.x;
    const int warp = tid >> 5;
    const int lane = tid & 31;
    const int tig  = lane & 3;
    const int grp  = lane >> 2;
    const int warp_m = (warp & 3) * 32;
    const int wn     = warp >> 2;        // 0/1: column half
    const int warp_n = wn * 64;
    const int row0 = blockIdx.x * 128;

    // fragment addresses (swizzle key collapses to lane&7)
    const int asw = lane & 7;
    const int akx = lane >> 4;
    const int bkx = (lane >> 3) & 1;
    uint32_t aB[2];
    #pragma unroll
    for (int mf = 0; mf < 2; mf++)
        aB[mf] = sbA + (warp_m + mf * 16 + ((lane >> 3) & 1) * 8 + (lane & 7)) * 512;
    uint32_t bBp[4];
    #pragma unroll
    for (int p = 0; p < 4; p++)
        bBp[p] = (uint32_t)((warp_n + p * 16 + (lane >> 4) * 8 + (lane & 7)) * 128);

    // ---- A staging: z rows -> bf16 swizzled smem ----
    #pragma unroll 4
    for (int i = 0; i < 16; i++) {
        int li = tid + i * 256;          // 4096 granules (16B = 8 bf16)
        int r = li >> 5, kg = li & 31;
        const float4* s = (const float4*)&z[(size_t)(row0 + r) * D_DIM + kg * 8];
        float4 v0 = s[0], v1 = s[1];
        *(uint4*)(smem + SMEM_A_OFF + r * 512 + ((kg ^ (r & 7)) << 4)) =
            make_uint4(bpack(v0.x, v0.y), bpack(v0.z, v0.w),
                       bpack(v1.x, v1.y), bpack(v1.z, v1.w));
    }
    // ---- B stage 0 via cp.async ----
    {
        const char* src = (const char*)g_cbb32;
        #pragma unroll
        for (int i = 0; i < 4; i++) {
            int li = tid + i * 256;
            int r = li >> 3, kg = li & 7;
            cp16(sbB + r * 128 + ((kg ^ (r & 7)) << 4), src + ((size_t)r * 256 + kg * 8) * 2);
        }
        CP_COMMIT();
    }
    CP_WAIT0();
    __syncthreads();

    float acc[2][8][4];
    #pragma unroll
    for (int mf = 0; mf < 2; mf++)
        #pragma unroll
        for (int nf = 0; nf < 8; nf++)
            #pragma unroll
            for (int q = 0; q < 4; q++) acc[mf][nf][q] = 0.f;

    // persistent per-thread top-3 for 4 row-slots (s = mf*2 + rh)
    unsigned long long P[4][3];
    #pragma unroll
    for (int s = 0; s < 4; s++) { P[s][0] = ~0ULL; P[s][1] = ~0ULL; P[s][2] = ~0ULL; }

    int pb = 0;
    #pragma unroll 1
    for (int st = 0; st < 32; st++) {
        const int t = st >> 2, ks = st & 3;

        // issue next B stage
        if (st < 31) {
            int stn = st + 1, tn = stn >> 2, ksn = stn & 3;
            const char* src = (const char*)g_cbb32 + ((size_t)(tn * 128) * 256 + ksn * 64) * 2;
            uint32_t dstb = sbB + (pb ^ 1) * 16384;
            #pragma unroll
            for (int i = 0; i < 4; i++) {
                int li = tid + i * 256;
                int r = li >> 3, kg = li & 7;
                cp16(dstb + r * 128 + ((kg ^ (r & 7)) << 4), src + ((size_t)r * 256 + kg * 8) * 2);
            }
            CP_COMMIT();
        }

        // compute current stage: 4 k16 slices
        const uint32_t bbuf = sbB + pb * 16384;
        #pragma unroll
        for (int k16 = 0; k16 < 4; k16++) {
            uint32_t kb = (uint32_t)(((k16 * 2 + bkx) ^ asw) << 4);
            unsigned bb[4][4];
            #pragma unroll
            for (int p = 0; p < 4; p++)
                LDSM4(bb[p][0], bb[p][1], bb[p][2], bb[p][3], bbuf + bBp[p] + kb);
            int kga = ks * 8 + k16 * 2 + akx;
            #pragma unroll
            for (int mf = 0; mf < 2; mf++) {
                unsigned a0, a1, a2, a3;
                LDSM4(a0, a1, a2, a3, aB[mf] + ((kga ^ asw) << 4));
                #pragma unroll
                for (int p = 0; p < 4; p++) {
                    mma_bf16(acc[mf][p * 2],     a0, a1, a2, a3, bb[p][0], bb[p][1]);
                    mma_bf16(acc[mf][p * 2 + 1], a0, a1, a2, a3, bb[p][2], bb[p][3]);
                }
            }
        }

        // ---- tile epilogue: distances -> per-thread register top-3 ----
        if (ks == 3) {
            int cbase = t * 128 + warp_n + tig * 2;
            #pragma unroll
            for (int nf = 0; nf < 8; nf++) {
                int ca = cbase + nf * 8;
                float cqa = __ldg(&g_csq[ca]);
                float cqb = __ldg(&g_csq[ca + 1]);
                #pragma unroll
                for (int mf = 0; mf < 2; mf++) {
                    #pragma unroll
                    for (int rh = 0; rh < 2; rh++) {
                        int s = mf * 2 + rh;
                        ins3(packdi(cqa - 2.f * acc[mf][nf][rh * 2],     ca),     P[s]);
                        ins3(packdi(cqb - 2.f * acc[mf][nf][rh * 2 + 1], ca + 1), P[s]);
                    }
                }
            }
            #pragma unroll
            for (int mf = 0; mf < 2; mf++)
                #pragma unroll
                for (int nf = 0; nf < 8; nf++)
                    #pragma unroll
                    for (int q = 0; q < 4; q++) acc[mf][nf][q] = 0.f;
        }

        CP_WAIT0();
        __syncthreads();
        pb ^= 1;
    }

    // ---- merge top-3 across tig lanes -> true half top-3 per row ----
    #pragma unroll
    for (int s = 0; s < 4; s++) {
        #pragma unroll
        for (int off = 1; off <= 2; off <<= 1) {
            unsigned long long ov[3];
            #pragma unroll
            for (int j = 0; j < 3; j++)
                ov[j] = __shfl_xor_sync(0xffffffffu, P[s][j], off);
            #pragma unroll
            for (int j = 0; j < 3; j++) ins3(ov[j], P[s]);
        }
        if (tig == 0) {
            int rl = warp_m + (s >> 1) * 16 + (s & 1) * 8 + grp;
            unsigned long long* c = candsm + (rl * 2 + wn) * 3;
            c[0] = P[s][0]; c[1] = P[s][1]; c[2] = P[s][2];
        }
    }
    __syncthreads();

    // ---- fused exact fp32 rescore of 6 candidates + scatter ----
    float lsum_t = 0.f;
    #pragma unroll 1
    for (int j = 0; j < 16; j++) {
        int lrow = warp * 16 + j;
        int row  = row0 + lrow;
        const float4* zp = (const float4*)&z[(size_t)row * D_DIM];
        float4 x0 = zp[lane], x1 = zp[lane + 32];

        float bd = FLT_BIG;
        int   bi = 0x7fffffff;
        #pragma unroll
        for (int c = 0; c < 6; c++) {
            int e = (int)(candsm[lrow * 6 + c] & 0xFFFFFFFFULL);
            const float4* cp = (const float4*)&cb[(size_t)e * D_DIM];
            float4 c0 = cp[lane], c1 = cp[lane + 32];
            float dot = x0.x*c0.x + x0.y*c0.y + x0.z*c0.z + x0.w*c0.w
                      + x1.x*c1.x + x1.y*c1.y + x1.z*c1.z + x1.w*c1.w;
            #pragma unroll
            for (int o = 16; o; o >>= 1) dot += __shfl_xor_sync(0xffffffffu, dot, o);
            float d = g_csq[e] - 2.f * dot;
            if (d < bd || (d == bd && e < bi)) { bd = d; bi = e; }
        }
        if (lane == 0) idx_f_out[row] = (float)bi;

        const float4* cp = (const float4*)&cb[(size_t)bi * D_DIM];
        float4 c0 = cp[lane], c1 = cp[lane + 32];
        float4 o0, o1;
        o0.x = x0.x + (c0.x - x0.x); o0.y = x0.y + (c0.y - x0.y);
        o0.z = x0.z + (c0.z - x0.z); o0.w = x0.w + (c0.w - x0.w);
        o1.x = x1.x + (c1.x - x1.x); o1.y = x1.y + (c1.y - x1.y);
        o1.z = x1.z + (c1.z - x1.z); o1.w = x1.w + (c1.w - x1.w);
        float4* qp = (float4*)&zq_out[(size_t)row * D_DIM];
        qp[lane] = o0; qp[lane + 32] = o1;

        float dx;
        dx = x0.x - c0.x; lsum_t += dx * dx;  dx = x0.y - c0.y; lsum_t += dx * dx;
        dx = x0.z - c0.z; lsum_t += dx * dx;  dx = x0.w - c0.w; lsum_t += dx * dx;
        dx = x1.x - c1.x; lsum_t += dx * dx;  dx = x1.y - c1.y; lsum_t += dx * dx;
        dx = x1.z - c1.z; lsum_t += dx * dx;  dx = x1.w - c1.w; lsum_t += dx * dx;

        float* ge = &g_embed[(size_t)bi * D_DIM];
        asm volatile("red.global.add.v4.f32 [%0], {%1,%2,%3,%4};"
                     :: "l"(ge + lane * 4), "f"(x0.x), "f"(x0.y), "f"(x0.z), "f"(x0.w) : "memory");
        asm volatile("red.global.add.v4.f32 [%0], {%1,%2,%3,%4};"
                     :: "l"(ge + (lane + 32) * 4), "f"(x1.x), "f"(x1.y), "f"(x1.z), "f"(x1.w) : "memory");
        if (lane == 0) atomicAdd(&g_counts[bi], 1.0f);
    }
    #pragma unroll
    for (int o = 16; o; o >>= 1) lsum_t += __shfl_xor_sync(0xffffffffu, lsum_t, o);
    if (lane == 0) atomicAdd(&g_loss, lsum_t);
}

// -------- merged finalize --------
__global__ void finalize_kernel(const float* __restrict__ ema_cs,
                                const float* __restrict__ ema_es,
                                float* __restrict__ out_cb,
                                float* __restrict__ out_cs,
                                float* __restrict__ out_es,
                                float* __restrict__ out_loss)
{
    int e = blockIdx.x;
    int d = threadIdx.x;  // 256
    float n = DECAY_F * g_nb + OMD_F * (float)N_TOT;
    float ncs = DECAY_F * ema_cs[e] + OMD_F * g_counts[e];
    float smoothed = (ncs + 1e-5f) / (n + 1024.0f * 1e-5f) * n;
    size_t i = (size_t)e * D_DIM + d;
    float nes = DECAY_F * ema_es[i] + OMD_F * g_embed[i];
    out_es[i] = nes;
    out_cb[i] = nes / smoothed;
    if (d == 0) {
        out_cs[e] = ncs;
        if (e == 0) *out_loss = 0.5f * g_loss / (float)(N_TOT * D_DIM);
    }
}

extern "C" void kernel_launch(void* const* d_in, const int* in_sizes, int n_in,
                              void* d_out, int out_size)
{
    const float* z_e    = (const float*)d_in[0];
    const float* cb     = (const float*)d_in[1];
    const float* ema_cs = (const float*)d_in[2];
    const float* ema_es = (const float*)d_in[3];
    float* out = (float*)d_out;

    float* out_zq   = out;
    float* out_loss = out + ZQ_ELEMS;
    float* out_idx  = out + ZQ_ELEMS + 1;
    float* out_cb   = out + ZQ_ELEMS + 1 + N_TOT;
    float* out_cs   = out_cb + E_NUM * D_DIM;
    float* out_es   = out_cs + E_NUM;

    cudaFuncSetAttribute(vq_main_kernel,
                         cudaFuncAttributeMaxDynamicSharedMemorySize, SMEM_TOTAL);

    csq_kernel<<<E_NUM + 1, 64>>>(cb, ema_cs);
    vq_main_kernel<<<N_TOT / 128, 256, SMEM_TOTAL>>>(z_e, cb, out_idx, out_zq);
    finalize_kernel<<<E_NUM, 256>>>(ema_cs, ema_es, out_cb, out_cs, out_es, out_loss);
}

// round 13
// speedup vs baseline: 4.9627x; 1.2402x over previous
#include <cuda_runtime.h>
#include <cstdint>

#define E_NUM 1024
#define D_DIM 256
#define N_TOT 32768
#define ZQ_ELEMS 8388608
#define DECAY_F 0.99f
#define OMD_F 0.01f
#define FLT_BIG 3.4e38f

// ---- dynamic smem layout (main kernel) ----
#define SMEM_A_OFF    0        // 65536 : A 128x256 bf16, swizzled
#define SMEM_B_OFF    65536    // 32768 : B double buffer, 2 x (128 codes x 64 k bf16)
#define SMEM_CAND_OFF 98304    // 3072  : cand [128 rows][2 halves][3] u32
#define SMEM_TOTAL    101376

// -------- device scratch (no allocations allowed) --------
__device__ float g_counts[E_NUM];
__device__ __align__(16) float g_embed[E_NUM * D_DIM];
__device__ float g_csq[E_NUM];
__device__ float g_loss;
__device__ float g_nb;
__device__ __align__(16) unsigned g_cbb32[E_NUM * D_DIM / 2];   // codebook bf16

// -------- helpers --------
__device__ __forceinline__ uint32_t smem_u32(const void* p) {
    uint32_t a;
    asm("{ .reg .u64 t; cvta.to.shared.u64 t, %1; cvt.u32.u64 %0, t; }" : "=r"(a) : "l"(p));
    return a;
}
__device__ __forceinline__ unsigned bpack(float lo, float hi) {
    unsigned r;
    asm("cvt.rn.bf16x2.f32 %0, %1, %2;" : "=r"(r) : "f"(hi), "f"(lo));
    return r;
}
__device__ __forceinline__ void mma_bf16(float* c, unsigned a0, unsigned a1, unsigned a2,
                                         unsigned a3, unsigned b0, unsigned b1) {
    asm volatile("mma.sync.aligned.m16n8k16.row.col.f32.bf16.bf16.f32 "
        "{%0,%1,%2,%3}, {%4,%5,%6,%7}, {%8,%9}, {%0,%1,%2,%3};"
        : "+f"(c[0]), "+f"(c[1]), "+f"(c[2]), "+f"(c[3])
        : "r"(a0), "r"(a1), "r"(a2), "r"(a3), "r"(b0), "r"(b1));
}
#define LDSM4(r0,r1,r2,r3,addr) \
    asm volatile("ldmatrix.sync.aligned.m8n8.x4.shared.b16 {%0,%1,%2,%3}, [%4];" \
        : "=r"(r0), "=r"(r1), "=r"(r2), "=r"(r3) : "r"(addr))
__device__ __forceinline__ void cp16(unsigned dst, const void* src) {
    asm volatile("cp.async.ca.shared.global [%0], [%1], 16;"
                 :: "r"(dst), "l"(__cvta_generic_to_global(src)) : "memory");
}
#define CP_COMMIT() asm volatile("cp.async.commit_group;" ::: "memory")
#define CP_WAIT0()  asm volatile("cp.async.wait_group 0;" ::: "memory")

// u32 key: orderable-f32(dist) top 22 bits | idx (10 bits). ascending == (dist, idx)
__device__ __forceinline__ unsigned packdi(float d, int idx) {
    unsigned u = __float_as_uint(d);
    u ^= (unsigned)(((int)u) >> 31) | 0x80000000u;
    return (u & 0xFFFFFC00u) | (unsigned)idx;
}
__device__ __forceinline__ void ins3(unsigned v, unsigned* p) {
    if (v < p[2]) {
        p[2] = v;
        if (p[2] < p[1]) { unsigned t = p[1]; p[1] = p[2]; p[2] = t; }
        if (p[1] < p[0]) { unsigned t = p[0]; p[0] = p[1]; p[1] = t; }
    }
}

// -------- csq + bf16 codebook + zero stats + ema_cs pre-sum --------
// grid 129 x 256: blocks 0-127 -> 8 codes each (warp per code); block 128 -> ema sum
__global__ void csq_kernel(const float* __restrict__ cb, const float* __restrict__ ema_cs) {
    int b = blockIdx.x;
    int warp = threadIdx.x >> 5;
    int lane = threadIdx.x & 31;
    if (b < 128) {
        int e = b * 8 + warp;
        const float4* src = (const float4*)&cb[(size_t)e * D_DIM];
        float4 v0 = src[lane * 2], v1 = src[lane * 2 + 1];
        ((uint4*)g_cbb32)[e * 32 + lane] =
            make_uint4(bpack(v0.x, v0.y), bpack(v0.z, v0.w),
                       bpack(v1.x, v1.y), bpack(v1.z, v1.w));
        float s = v0.x*v0.x + v0.y*v0.y + v0.z*v0.z + v0.w*v0.w
                + v1.x*v1.x + v1.y*v1.y + v1.z*v1.z + v1.w*v1.w;
        #pragma unroll
        for (int o = 16; o; o >>= 1) s += __shfl_xor_sync(0xffffffffu, s, o);
        float4 z4 = make_float4(0.f, 0.f, 0.f, 0.f);
        ((float4*)&g_embed[(size_t)e * D_DIM])[lane]      = z4;
        ((float4*)&g_embed[(size_t)e * D_DIM])[lane + 32] = z4;
        if (lane == 0) { g_csq[e] = s; g_counts[e] = 0.f; }
    } else {
        __shared__ float ws[8];
        float s = 0.f;
        for (int i = threadIdx.x; i < E_NUM; i += 256) s += ema_cs[i];
        #pragma unroll
        for (int o = 16; o; o >>= 1) s += __shfl_xor_sync(0xffffffffu, s, o);
        if (lane == 0) ws[warp] = s;
        __syncthreads();
        if (threadIdx.x == 0) {
            float t = 0.f;
            #pragma unroll
            for (int i = 0; i < 8; i++) t += ws[i];
            g_nb = t;
            g_loss = 0.f;
        }
    }
}

// -------- bf16 HMMA GEMM + register top-3 + fused exact rescore/scatter --------
// 256 threads = 8 warps; block tile 128 rows x 128 codes; warp tile 32x64.
// B streamed in K64 stages (32 stages, double buffered, 16 KB per buffer).
__global__ __launch_bounds__(256, 2) void vq_main_kernel(
    const float* __restrict__ z, const float* __restrict__ cb,
    float* __restrict__ idx_f_out, float* __restrict__ zq_out)
{
    extern __shared__ char smem[];
    const uint32_t sb  = smem_u32(smem);
    const uint32_t sbA = sb + SMEM_A_OFF;
    const uint32_t sbB = sb + SMEM_B_OFF;
    unsigned* candsm = (unsigned*)(smem + SMEM_CAND_OFF);

    const int tid  = threadIdx.x;
    const int warp = tid >> 5;
    const int lane = tid & 31;
    const int tig  = lane & 3;
    const int grp  = lane >> 2;
    const int warp_m = (warp & 3) * 32;
    const int wn     = warp >> 2;        // 0/1: column half
    const int warp_n = wn * 64;
    const int row0 = blockIdx.x * 128;

    // fragment addresses (swizzle key collapses to lane&7)
    const int asw = lane & 7;
    const int akx = lane >> 4;
    const int bkx = (lane >> 3) & 1;
    uint32_t aB[2];
    #pragma unroll
    for (int mf = 0; mf < 2; mf++)
        aB[mf] = sbA + (warp_m + mf * 16 + ((lane >> 3) & 1) * 8 + (lane & 7)) * 512;
    uint32_t bBp[4];
    #pragma unroll
    for (int p = 0; p < 4; p++)
        bBp[p] = (uint32_t)((warp_n + p * 16 + (lane >> 4) * 8 + (lane & 7)) * 128);

    // ---- A staging: z rows -> bf16 swizzled smem ----
    #pragma unroll 4
    for (int i = 0; i < 16; i++) {
        int li = tid + i * 256;          // 4096 granules (16B = 8 bf16)
        int r = li >> 5, kg = li & 31;
        const float4* s = (const float4*)&z[(size_t)(row0 + r) * D_DIM + kg * 8];
        float4 v0 = s[0], v1 = s[1];
        *(uint4*)(smem + SMEM_A_OFF + r * 512 + ((kg ^ (r & 7)) << 4)) =
            make_uint4(bpack(v0.x, v0.y), bpack(v0.z, v0.w),
                       bpack(v1.x, v1.y), bpack(v1.z, v1.w));
    }
    // ---- B stage 0 via cp.async (tile 0, K-quarter 0: 16 KB) ----
    {
        const char* src = (const char*)g_cbb32;
        #pragma unroll
        for (int i = 0; i < 4; i++) {
            int li = tid + i * 256;      // 1024 granules
            int r = li >> 3, kg = li & 7;
            cp16(sbB + r * 128 + ((kg ^ (r & 7)) << 4), src + (size_t)r * 512 + kg * 16);
        }
        CP_COMMIT();
    }
    CP_WAIT0();
    __syncthreads();

    float acc[2][8][4];
    #pragma unroll
    for (int mf = 0; mf < 2; mf++)
        #pragma unroll
        for (int nf = 0; nf < 8; nf++)
            #pragma unroll
            for (int q = 0; q < 4; q++) acc[mf][nf][q] = 0.f;

    // persistent per-thread top-3 (u32 packed) for 4 row-slots
    unsigned P[4][3];
    #pragma unroll
    for (int s = 0; s < 4; s++) { P[s][0] = ~0u; P[s][1] = ~0u; P[s][2] = ~0u; }

    int pb = 0;
    #pragma unroll 1
    for (int st = 0; st < 32; st++) {
        const int t = st >> 2, ks = st & 3;

        // issue next B stage (K64)
        if (st < 31) {
            int stn = st + 1, tn = stn >> 2, ksn = stn & 3;
            const char* src = (const char*)g_cbb32 + (size_t)(tn * 128) * 512 + ksn * 128;
            uint32_t dstb = sbB + (pb ^ 1) * 16384;
            #pragma unroll
            for (int i = 0; i < 4; i++) {
                int li = tid + i * 256;
                int r = li >> 3, kg = li & 7;
                cp16(dstb + r * 128 + ((kg ^ (r & 7)) << 4), src + (size_t)r * 512 + kg * 16);
            }
            CP_COMMIT();
        }

        // compute current stage: 4 k16 slices
        const uint32_t bbuf = sbB + pb * 16384;
        #pragma unroll
        for (int k16 = 0; k16 < 4; k16++) {
            uint32_t kb = (uint32_t)(((k16 * 2 + bkx) ^ asw) << 4);
            unsigned bb[4][4];
            #pragma unroll
            for (int p = 0; p < 4; p++)
                LDSM4(bb[p][0], bb[p][1], bb[p][2], bb[p][3], bbuf + bBp[p] + kb);
            int kga = ks * 8 + k16 * 2 + akx;
            #pragma unroll
            for (int mf = 0; mf < 2; mf++) {
                unsigned a0, a1, a2, a3;
                LDSM4(a0, a1, a2, a3, aB[mf] + ((kga ^ asw) << 4));
                #pragma unroll
                for (int p = 0; p < 4; p++) {
                    mma_bf16(acc[mf][p * 2],     a0, a1, a2, a3, bb[p][0], bb[p][1]);
                    mma_bf16(acc[mf][p * 2 + 1], a0, a1, a2, a3, bb[p][2], bb[p][3]);
                }
            }
        }

        // ---- tile epilogue: distances -> per-thread register top-3 ----
        if (ks == 3) {
            int cbase = t * 128 + warp_n + tig * 2;
            #pragma unroll
            for (int nf = 0; nf < 8; nf++) {
                int ca = cbase + nf * 8;
                float cqa = __ldg(&g_csq[ca]);
                float cqb = __ldg(&g_csq[ca + 1]);
                #pragma unroll
                for (int mf = 0; mf < 2; mf++) {
                    #pragma unroll
                    for (int rh = 0; rh < 2; rh++) {
                        int s = mf * 2 + rh;
                        ins3(packdi(cqa - 2.f * acc[mf][nf][rh * 2],     ca),     P[s]);
                        ins3(packdi(cqb - 2.f * acc[mf][nf][rh * 2 + 1], ca + 1), P[s]);
                    }
                }
            }
            #pragma unroll
            for (int mf = 0; mf < 2; mf++)
                #pragma unroll
                for (int nf = 0; nf < 8; nf++)
                    #pragma unroll
                    for (int q = 0; q < 4; q++) acc[mf][nf][q] = 0.f;
        }

        CP_WAIT0();
        __syncthreads();
        pb ^= 1;
    }

    // ---- merge top-3 across tig lanes -> half top-3 per row ----
    #pragma unroll
    for (int s = 0; s < 4; s++) {
        #pragma unroll
        for (int off = 1; off <= 2; off <<= 1) {
            unsigned ov[3];
            #pragma unroll
            for (int j = 0; j < 3; j++)
                ov[j] = __shfl_xor_sync(0xffffffffu, P[s][j], off);
            #pragma unroll
            for (int j = 0; j < 3; j++) ins3(ov[j], P[s]);
        }
        if (tig == 0) {
            int rl = warp_m + (s >> 1) * 16 + (s & 1) * 8 + grp;
            unsigned* c = candsm + (rl * 2 + wn) * 3;
            c[0] = P[s][0]; c[1] = P[s][1]; c[2] = P[s][2];
        }
    }
    __syncthreads();

    // ---- fused exact fp32 rescore of 6 candidates + scatter ----
    float lsum_t = 0.f;
    #pragma unroll 1
    for (int j = 0; j < 16; j++) {
        int lrow = warp * 16 + j;
        int row  = row0 + lrow;
        const float4* zp = (const float4*)&z[(size_t)row * D_DIM];
        float4 x0 = zp[lane], x1 = zp[lane + 32];

        float bd = FLT_BIG;
        int   bi = 0x7fffffff;
        #pragma unroll
        for (int c = 0; c < 6; c++) {
            int e = (int)(candsm[lrow * 6 + c] & 1023u);
            const float4* cp = (const float4*)&cb[(size_t)e * D_DIM];
            float4 c0 = cp[lane], c1 = cp[lane + 32];
            float dot = x0.x*c0.x + x0.y*c0.y + x0.z*c0.z + x0.w*c0.w
                      + x1.x*c1.x + x1.y*c1.y + x1.z*c1.z + x1.w*c1.w;
            #pragma unroll
            for (int o = 16; o; o >>= 1) dot += __shfl_xor_sync(0xffffffffu, dot, o);
            float d = g_csq[e] - 2.f * dot;
            if (d < bd || (d == bd && e < bi)) { bd = d; bi = e; }
        }
        if (lane == 0) idx_f_out[row] = (float)bi;

        const float4* cp = (const float4*)&cb[(size_t)bi * D_DIM];
        float4 c0 = cp[lane], c1 = cp[lane + 32];
        float4 o0, o1;
        o0.x = x0.x + (c0.x - x0.x); o0.y = x0.y + (c0.y - x0.y);
        o0.z = x0.z + (c0.z - x0.z); o0.w = x0.w + (c0.w - x0.w);
        o1.x = x1.x + (c1.x - x1.x); o1.y = x1.y + (c1.y - x1.y);
        o1.z = x1.z + (c1.z - x1.z); o1.w = x1.w + (c1.w - x1.w);
        float4* qp = (float4*)&zq_out[(size_t)row * D_DIM];
        qp[lane] = o0; qp[lane + 32] = o1;

        float dx;
        dx = x0.x - c0.x; lsum_t += dx * dx;  dx = x0.y - c0.y; lsum_t += dx * dx;
        dx = x0.z - c0.z; lsum_t += dx * dx;  dx = x0.w - c0.w; lsum_t += dx * dx;
        dx = x1.x - c1.x; lsum_t += dx * dx;  dx = x1.y - c1.y; lsum_t += dx * dx;
        dx = x1.z - c1.z; lsum_t += dx * dx;  dx = x1.w - c1.w; lsum_t += dx * dx;

        float* ge = &g_embed[(size_t)bi * D_DIM];
        asm volatile("red.global.add.v4.f32 [%0], {%1,%2,%3,%4};"
                     :: "l"(ge + lane * 4), "f"(x0.x), "f"(x0.y), "f"(x0.z), "f"(x0.w) : "memory");
        asm volatile("red.global.add.v4.f32 [%0], {%1,%2,%3,%4};"
                     :: "l"(ge + (lane + 32) * 4), "f"(x1.x), "f"(x1.y), "f"(x1.z), "f"(x1.w) : "memory");
        if (lane == 0) atomicAdd(&g_counts[bi], 1.0f);
    }
    #pragma unroll
    for (int o = 16; o; o >>= 1) lsum_t += __shfl_xor_sync(0xffffffffu, lsum_t, o);
    if (lane == 0) atomicAdd(&g_loss, lsum_t);
}

// -------- merged finalize (vector loads, scalar stores: outputs are odd-offset) --------
__global__ void finalize_kernel(const float* __restrict__ ema_cs,
                                const float* __restrict__ ema_es,
                                float* __restrict__ out_cb,
                                float* __restrict__ out_cs,
                                float* __restrict__ out_es,
                                float* __restrict__ out_loss)
{
    int e = blockIdx.x * 4 + (threadIdx.x >> 6);
    int q = threadIdx.x & 63;   // float4 slot within the code row
    float n = DECAY_F * g_nb + OMD_F * (float)N_TOT;
    float ncs = DECAY_F * ema_cs[e] + OMD_F * g_counts[e];
    float inv_sm = (n + 1024.0f * 1e-5f) / ((ncs + 1e-5f) * n);
    size_t base = (size_t)e * D_DIM + q * 4;
    float4 es = *(const float4*)&ema_es[base];      // inputs: 16B-aligned
    float4 ge = *(const float4*)&g_embed[base];
    float nes0 = DECAY_F * es.x + OMD_F * ge.x;
    float nes1 = DECAY_F * es.y + OMD_F * ge.y;
    float nes2 = DECAY_F * es.z + OMD_F * ge.z;
    float nes3 = DECAY_F * es.w + OMD_F * ge.w;
    // outputs live at odd float offsets in d_out -> scalar stores only
    out_es[base + 0] = nes0;  out_cb[base + 0] = nes0 * inv_sm;
    out_es[base + 1] = nes1;  out_cb[base + 1] = nes1 * inv_sm;
    out_es[base + 2] = nes2;  out_cb[base + 2] = nes2 * inv_sm;
    out_es[base + 3] = nes3;  out_cb[base + 3] = nes3 * inv_sm;
    if (q == 0) {
        out_cs[e] = ncs;
        if (e == 0) *out_loss = 0.5f * g_loss / (float)(N_TOT * D_DIM);
    }
}

extern "C" void kernel_launch(void* const* d_in, const int* in_sizes, int n_in,
                              void* d_out, int out_size)
{
    const float* z_e    = (const float*)d_in[0];
    const float* cb     = (const float*)d_in[1];
    const float* ema_cs = (const float*)d_in[2];
    const float* ema_es = (const float*)d_in[3];
    float* out = (float*)d_out;

    float* out_zq   = out;
    float* out_loss = out + ZQ_ELEMS;
    float* out_idx  = out + ZQ_ELEMS + 1;
    float* out_cb   = out + ZQ_ELEMS + 1 + N_TOT;
    float* out_cs   = out_cb + E_NUM * D_DIM;
    float* out_es   = out_cs + E_NUM;

    cudaFuncSetAttribute(vq_main_kernel,
                         cudaFuncAttributeMaxDynamicSharedMemorySize, SMEM_TOTAL);

    csq_kernel<<<129, 256>>>(cb, ema_cs);
    vq_main_kernel<<<N_TOT / 128, 256, SMEM_TOTAL>>>(z_e, cb, out_idx, out_zq);
    finalize_kernel<<<E_NUM / 4, 256>>>(ema_cs, ema_es, out_cb, out_cs, out_es, out_loss);
}